// round 4
// baseline (speedup 1.0000x reference)
#include <cuda_runtime.h>
#include <cuda_fp16.h>
#include <cstdint>

// ============================================================================
// Problem sizes
// ============================================================================
static constexpr int NVOX  = 65536;
static constexpr int CIN   = 64;
static constexpr int CH    = 64;
static constexpr int COUT3 = 16;
static constexpr int KOFF  = 27;
static constexpr int TM    = 256;            // voxel rows per CTA tile
static constexpr int NTILE = NVOX / TM;      // 256
static constexpr int NGRP  = TM / 16;        // 16 m16 groups per tile

// ============================================================================
// Device scratch (no dynamic allocation allowed)
// ============================================================================
__device__ __half g_xh[NVOX * CIN];
__device__ __half g_h1[NVOX * CH];
__device__ __half g_h2[NVOX * CH];
// weights pre-packed in mma.m16n8k16 B-fragment order:
// [k][ko][no][lane] -> uint2 (4 halves)
__device__ __half g_W1f[KOFF * CH * CIN];
__device__ __half g_W2f[KOFF * CH * CH];
__device__ __half g_W3f[KOFF * COUT3 * CH];

// ============================================================================
// PTX helpers (portable sm_100 subset: cp.async + ldmatrix + mma.sync)
// ============================================================================
__device__ __forceinline__ uint32_t smem_to_u32(const void* smem_ptr) {
    uint32_t addr;
    asm("{ .reg .u64 tmp; cvta.to.shared.u64 tmp, %1; cvt.u32.u64 %0, tmp; }"
        : "=r"(addr) : "l"(smem_ptr));
    return addr;
}

__device__ __forceinline__ void cp_async16(uint32_t dst, const void* src) {
    asm volatile("cp.async.cg.shared.global [%0], [%1], 16;"
                 :: "r"(dst), "l"(src));
}
__device__ __forceinline__ void cp_commit() {
    asm volatile("cp.async.commit_group;");
}
template <int N>
__device__ __forceinline__ void cp_wait() {
    asm volatile("cp.async.wait_group %0;" :: "n"(N));
}

__device__ __forceinline__ void ldmatrix_x4(uint32_t* a, uint32_t addr) {
    asm volatile("ldmatrix.sync.aligned.m8n8.x4.shared.b16 {%0,%1,%2,%3}, [%4];"
                 : "=r"(a[0]), "=r"(a[1]), "=r"(a[2]), "=r"(a[3]) : "r"(addr));
}

__device__ __forceinline__ void mma16816(float* c, const uint32_t* a,
                                         const uint32_t* b) {
    asm volatile(
        "mma.sync.aligned.m16n8k16.row.col.f32.f16.f16.f32 "
        "{%0,%1,%2,%3}, {%4,%5,%6,%7}, {%8,%9}, {%0,%1,%2,%3};"
        : "+f"(c[0]), "+f"(c[1]), "+f"(c[2]), "+f"(c[3])
        : "r"(a[0]), "r"(a[1]), "r"(a[2]), "r"(a[3]), "r"(b[0]), "r"(b[1]));
}

// ============================================================================
// SMEM layout (bytes, within dynamic smem)
// ============================================================================
static constexpr int SMEM_GMASK = 0;                      // NGRP u32
static constexpr int SMEM_VMASK = 128;                    // TM u32 = 1024B
static constexpr int SMEM_IDX   = 1280;                   // 27*256*4 = 27648
static constexpr int SMEM_A     = 30720;                  // 1024-aligned
static constexpr int A_BYTES    = TM * 128;               // 32768
static constexpr int SMEM_B     = SMEM_A + 2 * A_BYTES;   // 96256
// total = SMEM_B + 2*COUT*128

// ============================================================================
// One sparse-conv layer: out[n,:] = act( sum_k feat[nidx[n,k],:] @ W[k] + b )
// 8 warps per CTA, each warp: m32 x nCOUT, fp32 accum in registers.
// Gather ONLY valid rows (no zero-fill); garbage SMEM rows are masked in the
// MMA A-fragments via per-row validity bits. Whole-m16-group slabs skipped.
// ============================================================================
template <int COUT, bool RELU, typename OUT_T>
__global__ void __launch_bounds__(256, 2)
layer_kernel(const __half* __restrict__ feat,
             const int*    __restrict__ nidx,
             const __half* __restrict__ Wf,
             const float*  __restrict__ bias,
             OUT_T*        __restrict__ out)
{
    constexpr int NO      = COUT / 8;        // n8 tiles per warp
    constexpr int B_BYTES = COUT * 128;      // 64(k) * COUT * 2B per offset
    extern __shared__ char smem[];
    const uint32_t smem_base = smem_to_u32(smem);
    const int tid  = threadIdx.x;
    const int wid  = tid >> 5;
    const int lane = tid & 31;
    const int base_row = blockIdx.x * TM;

    int*      s_idx   = (int*)(smem + SMEM_IDX);
    uint32_t* s_gmask = (uint32_t*)(smem + SMEM_GMASK);
    uint32_t* s_vmask = (uint32_t*)(smem + SMEM_VMASK);

    if (tid < NGRP) s_gmask[tid] = 0u;
    __syncthreads();

    // ---- stage neighbor indices (transposed to [k][row]) + validity masks ----
    {
        const int* ip = nidx + (size_t)(base_row + tid) * KOFF;
        uint32_t m = 0;
        #pragma unroll
        for (int kk = 0; kk < KOFF; kk++) {
            int nb = ip[kk];
            s_idx[kk * TM + tid] = nb;
            m |= (uint32_t)(nb >= 0) << kk;
        }
        s_vmask[tid] = m;
        atomicOr((int*)&s_gmask[tid >> 4], (int)m);
    }
    __syncthreads();

    const char* bsrc_base = (const char*)Wf;

    // ---- gather stage for offset k into buffer buf (valid rows only) ----
    auto stage = [&](int k, int buf) {
        int nb = s_idx[k * TM + tid];
        if (nb >= 0) {
            const char* src = (const char*)(feat + (size_t)nb * 64);
            uint32_t drow = smem_base + SMEM_A + buf * A_BYTES + tid * 128;
            uint32_t sw = (uint32_t)(tid & 7) * 16;
            #pragma unroll
            for (int c = 0; c < 8; c++)
                cp_async16(drow + (((uint32_t)(c * 16)) ^ sw), src + c * 16);
        }
        // B: linear copy of this offset's fragment-ordered weight tile
        {
            const char* bs = bsrc_base + (size_t)k * B_BYTES;
            uint32_t bd = smem_base + SMEM_B + buf * B_BYTES;
            #pragma unroll
            for (int j = tid; j < B_BYTES / 16; j += 256)
                cp_async16(bd + j * 16, bs + (size_t)j * 16);
        }
        cp_commit();
    };

    float acc[2][NO][4];
    #pragma unroll
    for (int mt = 0; mt < 2; mt++)
        #pragma unroll
        for (int no = 0; no < NO; no++)
            #pragma unroll
            for (int r = 0; r < 4; r++)
                acc[mt][no][r] = 0.f;

    stage(0, 0);

    const int m0 = wid * 32;
    for (int k = 0; k < KOFF; k++) {
        const int buf = k & 1;
        if (k + 1 < KOFF) { stage(k + 1, buf ^ 1); cp_wait<1>(); }
        else              { cp_wait<0>(); }
        __syncthreads();

        const uint32_t v0 = (s_gmask[2 * wid]     >> k) & 1u;
        const uint32_t v1 = (s_gmask[2 * wid + 1] >> k) & 1u;
        if (v0 | v1) {
            const uint32_t aBase = smem_base + SMEM_A + buf * A_BYTES;
            const uint32_t bBase = smem_base + SMEM_B + buf * B_BYTES;
            // per-lane row validity for fragment masking
            // regs {0,2} belong to row g=lane>>2, regs {1,3} to row g+8
            uint32_t lo0 = 0, hi0 = 0, lo1 = 0, hi1 = 0;
            if (v0) {
                lo0 = (s_vmask[m0 + (lane >> 2)]      >> k) & 1u;
                hi0 = (s_vmask[m0 + (lane >> 2) + 8]  >> k) & 1u;
            }
            if (v1) {
                lo1 = (s_vmask[m0 + 16 + (lane >> 2)]     >> k) & 1u;
                hi1 = (s_vmask[m0 + 16 + (lane >> 2) + 8] >> k) & 1u;
            }
            #pragma unroll
            for (int ko = 0; ko < 4; ko++) {
                uint32_t afrag[2][4];
                const int ch = ko * 2 + (lane >> 4);
                if (v0) {
                    int r = m0 + (lane & 15);
                    ldmatrix_x4(afrag[0],
                        aBase + r * 128 + (((uint32_t)ch ^ (uint32_t)(r & 7)) * 16));
                    if (!lo0) { afrag[0][0] = 0u; afrag[0][2] = 0u; }
                    if (!hi0) { afrag[0][1] = 0u; afrag[0][3] = 0u; }
                }
                if (v1) {
                    int r = m0 + 16 + (lane & 15);
                    ldmatrix_x4(afrag[1],
                        aBase + r * 128 + (((uint32_t)ch ^ (uint32_t)(r & 7)) * 16));
                    if (!lo1) { afrag[1][0] = 0u; afrag[1][2] = 0u; }
                    if (!hi1) { afrag[1][1] = 0u; afrag[1][3] = 0u; }
                }
                #pragma unroll
                for (int no = 0; no < NO; no++) {
                    uint32_t b[2];
                    asm volatile("ld.shared.v2.b32 {%0,%1}, [%2];"
                                 : "=r"(b[0]), "=r"(b[1])
                                 : "r"(bBase + ((ko * NO + no) * 32 + lane) * 8));
                    if (v0) mma16816(acc[0][no], afrag[0], b);
                    if (v1) mma16816(acc[1][no], afrag[1], b);
                }
            }
        }
        __syncthreads();
    }

    // ---- epilogue: +bias, activation, store ----
    float2 bb[NO];
    #pragma unroll
    for (int no = 0; no < NO; no++) {
        int c0 = no * 8 + (lane & 3) * 2;
        bb[no].x = bias[c0];
        bb[no].y = bias[c0 + 1];
    }
    #pragma unroll
    for (int mt = 0; mt < 2; mt++) {
        int r0 = base_row + m0 + mt * 16 + (lane >> 2);
        #pragma unroll
        for (int no = 0; no < NO; no++) {
            int c0 = no * 8 + (lane & 3) * 2;
            float f0 = acc[mt][no][0] + bb[no].x;
            float f1 = acc[mt][no][1] + bb[no].y;
            float f2 = acc[mt][no][2] + bb[no].x;
            float f3 = acc[mt][no][3] + bb[no].y;
            if (RELU) {
                f0 = fmaxf(f0, 0.f); f1 = fmaxf(f1, 0.f);
                f2 = fmaxf(f2, 0.f); f3 = fmaxf(f3, 0.f);
            }
            if constexpr (sizeof(OUT_T) == 2) {
                __half2* o0 = (__half2*)((__half*)out + (size_t)r0 * COUT + c0);
                __half2* o1 = (__half2*)((__half*)out + (size_t)(r0 + 8) * COUT + c0);
                *o0 = __floats2half2_rn(f0, f1);
                *o1 = __floats2half2_rn(f2, f3);
            } else {
                float2* o0 = (float2*)((float*)out + (size_t)r0 * COUT + c0);
                float2* o1 = (float2*)((float*)out + (size_t)(r0 + 8) * COUT + c0);
                *o0 = make_float2(f0, f1);
                *o1 = make_float2(f2, f3);
            }
        }
    }
}

// ============================================================================
// Fused prologue: x -> fp16, and W1/W2/W3 -> mma B-fragment order
//   fragment task i: [k][ko][no][lane] -> uint2 of 4 halves
//     .x = (B[kk0][n], B[kk0+1][n])   .y = (B[kk0+8][n], B[kk0+9][n])
//     kk0 = ko*16 + (lane%4)*2,  n = no*8 + lane/4
// ============================================================================
__device__ __forceinline__ void prep_b_elem(const float* __restrict__ W,
                                            __half* __restrict__ Bf,
                                            int Cout, int i) {
    int NOv  = Cout / 8;
    int lane = i & 31;
    int g    = i >> 5;
    int no   = g % NOv;
    int ko   = (g / NOv) % 4;
    int k    = g / (NOv * 4);
    int n    = no * 8 + (lane >> 2);
    int kk0  = ko * 16 + (lane & 3) * 2;
    const float* Wk = W + (size_t)k * 64 * Cout;
    __half h0 = __float2half_rn(Wk[(kk0 + 0) * Cout + n]);
    __half h1 = __float2half_rn(Wk[(kk0 + 1) * Cout + n]);
    __half h2 = __float2half_rn(Wk[(kk0 + 8) * Cout + n]);
    __half h3 = __float2half_rn(Wk[(kk0 + 9) * Cout + n]);
    uint2 v;
    v.x = (uint32_t)__half_as_ushort(h0) | ((uint32_t)__half_as_ushort(h1) << 16);
    v.y = (uint32_t)__half_as_ushort(h2) | ((uint32_t)__half_as_ushort(h3) << 16);
    ((uint2*)Bf)[i] = v;
}

static constexpr int PREP_NP  = NVOX * CIN / 2;        // x half2 pairs
static constexpr int PREP_T12 = KOFF * 4 * 8 * 32;     // W1/W2 frag tasks
static constexpr int PREP_T3  = KOFF * 4 * 2 * 32;     // W3 frag tasks
static constexpr int PREP_TOT = PREP_NP + 2 * PREP_T12 + PREP_T3;

__global__ void k_prep(const float* __restrict__ x, __half* __restrict__ xh,
                       const float* __restrict__ W1, __half* __restrict__ w1f,
                       const float* __restrict__ W2, __half* __restrict__ w2f,
                       const float* __restrict__ W3, __half* __restrict__ w3f) {
    int i = blockIdx.x * blockDim.x + threadIdx.x;
    if (i < PREP_NP) {
        float2 v = ((const float2*)x)[i];
        ((__half2*)xh)[i] = __floats2half2_rn(v.x, v.y);
    } else if (i < PREP_NP + PREP_T12) {
        prep_b_elem(W1, w1f, 64, i - PREP_NP);
    } else if (i < PREP_NP + 2 * PREP_T12) {
        prep_b_elem(W2, w2f, 64, i - PREP_NP - PREP_T12);
    } else if (i < PREP_TOT) {
        prep_b_elem(W3, w3f, 16, i - PREP_NP - 2 * PREP_T12);
    }
}

// ============================================================================
// kernel_launch
// ============================================================================
extern "C" void kernel_launch(void* const* d_in, const int* in_sizes, int n_in,
                              void* d_out, int out_size) {
    const float* x    = (const float*)d_in[0];
    const int*   nidx = (const int*)  d_in[1];
    const float* W1   = (const float*)d_in[2];
    const float* b1   = (const float*)d_in[3];
    const float* W2   = (const float*)d_in[4];
    const float* b2   = (const float*)d_in[5];
    const float* W3   = (const float*)d_in[6];
    const float* b3   = (const float*)d_in[7];

    __half *xh, *h1, *h2, *w1f, *w2f, *w3f;
    cudaGetSymbolAddress((void**)&xh,  g_xh);
    cudaGetSymbolAddress((void**)&h1,  g_h1);
    cudaGetSymbolAddress((void**)&h2,  g_h2);
    cudaGetSymbolAddress((void**)&w1f, g_W1f);
    cudaGetSymbolAddress((void**)&w2f, g_W2f);
    cudaGetSymbolAddress((void**)&w3f, g_W3f);

    constexpr int SZ64 = SMEM_B + 2 * 64 * 128;  // 112640
    constexpr int SZ16 = SMEM_B + 2 * 16 * 128;  // 100352
    cudaFuncSetAttribute((const void*)layer_kernel<64, true,  __half>,
                         cudaFuncAttributeMaxDynamicSharedMemorySize, SZ64);
    cudaFuncSetAttribute((const void*)layer_kernel<16, false, float>,
                         cudaFuncAttributeMaxDynamicSharedMemorySize, SZ16);

    k_prep<<<(PREP_TOT + 255) / 256, 256>>>(x, xh, W1, w1f, W2, w2f, W3, w3f);

    layer_kernel<64, true,  __half><<<NTILE, 256, SZ64>>>(xh, nidx, w1f, b1, h1);
    layer_kernel<64, true,  __half><<<NTILE, 256, SZ64>>>(h1, nidx, w2f, b2, h2);
    layer_kernel<16, false, float ><<<NTILE, 256, SZ16>>>(h2, nidx, w3f, b3,
                                                          (float*)d_out);
}

// round 5
// speedup vs baseline: 1.3480x; 1.3480x over previous
#include <cuda_runtime.h>
#include <cuda_fp16.h>
#include <cstdint>

// ============================================================================
// Problem sizes
// ============================================================================
static constexpr int NVOX  = 65536;
static constexpr int CIN   = 64;
static constexpr int CH    = 64;
static constexpr int COUT3 = 16;
static constexpr int KOFF  = 27;
static constexpr int NBLK  = 256;             // rows per count/fill block
static constexpr int NROWB = NVOX / NBLK;     // 256 blocks
static constexpr int PMAX  = KOFF * NVOX;     // worst-case pair count
static constexpr int TILE  = 256;             // pair rows per phase-A tile
static constexpr int TMAXT = KOFF * (NVOX / TILE);  // worst-case tiles

// ============================================================================
// Device scratch (no dynamic allocation allowed)
// ============================================================================
__device__ __half g_xh[NVOX * CIN];
__device__ __half g_h1[NVOX * CH];
__device__ __half g_h2[NVOX * CH];
__device__ __half g_W1f[KOFF * CH * CIN];
__device__ __half g_W2f[KOFF * CH * CH];
__device__ __half g_W3f[KOFF * COUT3 * CH];

__device__ int    g_inlist[PMAX];                   // input row per pair
__device__ __half g_partial[(size_t)PMAX * 64];     // pair partial rows
__device__ int    g_rowpairs[NVOX * KOFF];          // per-row pair ids
__device__ int    g_rcnt[NVOX];
__device__ int    g_blockcnt[NROWB * KOFF];
__device__ int    g_blockbase[NROWB * KOFF];
__device__ int2   g_tiles[TMAXT];                   // {start, k | cnt<<8}
__device__ int    g_ntiles[1];

// ============================================================================
// PTX helpers
// ============================================================================
__device__ __forceinline__ uint32_t smem_to_u32(const void* smem_ptr) {
    uint32_t addr;
    asm("{ .reg .u64 tmp; cvta.to.shared.u64 tmp, %1; cvt.u32.u64 %0, tmp; }"
        : "=r"(addr) : "l"(smem_ptr));
    return addr;
}
__device__ __forceinline__ void cp_async16(uint32_t dst, const void* src) {
    asm volatile("cp.async.cg.shared.global [%0], [%1], 16;"
                 :: "r"(dst), "l"(src));
}
__device__ __forceinline__ void cp_commit() {
    asm volatile("cp.async.commit_group;");
}
template <int N>
__device__ __forceinline__ void cp_wait() {
    asm volatile("cp.async.wait_group %0;" :: "n"(N));
}
__device__ __forceinline__ void ldmatrix_x4(uint32_t* a, uint32_t addr) {
    asm volatile("ldmatrix.sync.aligned.m8n8.x4.shared.b16 {%0,%1,%2,%3}, [%4];"
                 : "=r"(a[0]), "=r"(a[1]), "=r"(a[2]), "=r"(a[3]) : "r"(addr));
}
__device__ __forceinline__ void mma16816(float* c, const uint32_t* a,
                                         const uint32_t* b) {
    asm volatile(
        "mma.sync.aligned.m16n8k16.row.col.f32.f16.f16.f32 "
        "{%0,%1,%2,%3}, {%4,%5,%6,%7}, {%8,%9}, {%0,%1,%2,%3};"
        : "+f"(c[0]), "+f"(c[1]), "+f"(c[2]), "+f"(c[3])
        : "r"(a[0]), "r"(a[1]), "r"(a[2]), "r"(a[3]), "r"(b[0]), "r"(b[1]));
}

// ============================================================================
// Pair-list construction (deterministic, built once per launch)
// ============================================================================
__global__ void __launch_bounds__(NBLK)
k_count(const int* __restrict__ nidx, int* __restrict__ blockcnt) {
    __shared__ int scnt[KOFF];
    const int t = threadIdx.x, b = blockIdx.x;
    if (t < KOFF) scnt[t] = 0;
    __syncthreads();
    const int row = b * NBLK + t;
    const int* ip = nidx + (size_t)row * KOFF;
    unsigned m = 0;
    #pragma unroll
    for (int k = 0; k < KOFF; k++)
        m |= (unsigned)(ip[k] >= 0) << k;
    #pragma unroll
    for (int k = 0; k < KOFF; k++) {
        unsigned bal = __ballot_sync(0xFFFFFFFFu, (m >> k) & 1u);
        if ((t & 31) == 0) atomicAdd(&scnt[k], __popc(bal));
    }
    __syncthreads();
    if (t < KOFF) blockcnt[b * KOFF + t] = scnt[t];
}

__global__ void __launch_bounds__(256)
k_scan(const int* __restrict__ blockcnt, int* __restrict__ blockbase,
       int2* __restrict__ tiles, int* __restrict__ ntiles) {
    __shared__ int cntk[KOFF], kbase[KOFF], tcnt[KOFF], tbase[KOFF];
    const int t = threadIdx.x;
    if (t < KOFF) {
        int s = 0;
        for (int b = 0; b < NROWB; b++) s += blockcnt[b * KOFF + t];
        cntk[t] = s;
    }
    __syncthreads();
    if (t == 0) {
        int run = 0, trun = 0;
        for (int k = 0; k < KOFF; k++) {
            kbase[k] = run;  run  += cntk[k];
            tcnt[k]  = (cntk[k] + TILE - 1) / TILE;
            tbase[k] = trun; trun += tcnt[k];
        }
        *ntiles = trun;
    }
    __syncthreads();
    if (t < KOFF) {
        for (int j = 0; j < tcnt[t]; j++) {
            int st = kbase[t] + j * TILE;
            int c  = min(TILE, cntk[t] - j * TILE);
            tiles[tbase[t] + j] = make_int2(st, t | (c << 8));
        }
        int run = kbase[t];
        for (int b = 0; b < NROWB; b++) {
            blockbase[b * KOFF + t] = run;
            run += blockcnt[b * KOFF + t];
        }
    }
}

__global__ void __launch_bounds__(NBLK)
k_fill(const int* __restrict__ nidx, const int* __restrict__ blockbase,
       int* __restrict__ inlist, int* __restrict__ rowpairs,
       int* __restrict__ rcnt) {
    __shared__ int wcnt[KOFF][NBLK / 32];
    const int t = threadIdx.x, b = blockIdx.x;
    const int w = t >> 5, lane = t & 31;
    const int row = b * NBLK + t;
    const int* ip = nidx + (size_t)row * KOFF;
    int nb[KOFF];
    unsigned m = 0;
    #pragma unroll
    for (int k = 0; k < KOFF; k++) {
        nb[k] = ip[k];
        m |= (unsigned)(nb[k] >= 0) << k;
    }
    #pragma unroll
    for (int k = 0; k < KOFF; k++) {
        unsigned bal = __ballot_sync(0xFFFFFFFFu, (m >> k) & 1u);
        if (lane == 0) wcnt[k][w] = __popc(bal);
    }
    __syncthreads();
    int slot = 0;
    const unsigned lt = (lane == 0) ? 0u : (0xFFFFFFFFu >> (32 - lane));
    #pragma unroll
    for (int k = 0; k < KOFF; k++) {
        unsigned bal = __ballot_sync(0xFFFFFFFFu, (m >> k) & 1u);
        if ((m >> k) & 1u) {
            int rank = __popc(bal & lt);
            for (int w2 = 0; w2 < w; w2++) rank += wcnt[k][w2];
            int p = blockbase[b * KOFF + k] + rank;
            inlist[p] = nb[k];
            rowpairs[(size_t)row * KOFF + slot] = p;
            slot++;
        }
    }
    rcnt[row] = slot;
}

// ============================================================================
// Phase A: per tile (one k), partial[p,:] = feat[inlist[p],:] @ W[k]
// ============================================================================
template <int COUT>
__global__ void __launch_bounds__(256)
phaseA(const __half* __restrict__ feat, const __half* __restrict__ Wf,
       const int* __restrict__ inlist, const int2* __restrict__ tiles,
       const int* __restrict__ ntiles_p, __half* __restrict__ partial)
{
    constexpr int NO      = COUT / 8;
    constexpr int B_BYTES = COUT * 128;
    constexpr int SMEM_BB = TILE * 128;         // A tile bytes
    extern __shared__ char smem[];
    const uint32_t smem_base = smem_to_u32(smem);
    const int tid  = threadIdx.x;
    const int wid  = tid >> 5;
    const int lane = tid & 31;
    const int nt   = *ntiles_p;
    const int m0   = wid * 32;

    for (int t = blockIdx.x; t < nt; t += gridDim.x) {
        const int2 d   = tiles[t];
        const int start = d.x;
        const int k     = d.y & 31;
        const int cnt   = d.y >> 8;

        // stage B = Wf[k] (fragment-ordered, linear copy)
        {
            const char* bs = (const char*)Wf + (size_t)k * B_BYTES;
            for (int j = tid; j < B_BYTES / 16; j += 256)
                cp_async16(smem_base + SMEM_BB + j * 16, bs + (size_t)j * 16);
        }
        // stage A: thread tid gathers pair row tid of this tile
        if (tid < cnt) {
            int in_row = inlist[start + tid];
            const char* src = (const char*)(feat + (size_t)in_row * 64);
            uint32_t drow = smem_base + tid * 128;
            uint32_t sw = (uint32_t)(tid & 7) * 16;
            #pragma unroll
            for (int c = 0; c < 8; c++)
                cp_async16(drow + (((uint32_t)(c * 16)) ^ sw), src + c * 16);
        }
        cp_commit();
        cp_wait<0>();
        __syncthreads();

        float acc[2][NO][4];
        #pragma unroll
        for (int mt = 0; mt < 2; mt++)
            #pragma unroll
            for (int no = 0; no < NO; no++)
                #pragma unroll
                for (int r = 0; r < 4; r++)
                    acc[mt][no][r] = 0.f;

        #pragma unroll
        for (int ko = 0; ko < 4; ko++) {
            uint32_t afrag[2][4];
            const int ch = ko * 2 + (lane >> 4);
            #pragma unroll
            for (int mt = 0; mt < 2; mt++) {
                int r = m0 + mt * 16 + (lane & 15);
                ldmatrix_x4(afrag[mt],
                    smem_base + r * 128 + (((uint32_t)ch ^ (uint32_t)(r & 7)) * 16));
            }
            #pragma unroll
            for (int no = 0; no < NO; no++) {
                uint32_t b[2];
                asm volatile("ld.shared.v2.b32 {%0,%1}, [%2];"
                             : "=r"(b[0]), "=r"(b[1])
                             : "r"(smem_base + SMEM_BB +
                                   ((ko * NO + no) * 32 + lane) * 8));
                mma16816(acc[0][no], afrag[0], b);
                mma16816(acc[1][no], afrag[1], b);
            }
        }

        // write partial rows (fp16), guarded against tile tail
        #pragma unroll
        for (int mt = 0; mt < 2; mt++) {
            const int lr = m0 + mt * 16 + (lane >> 2);
            #pragma unroll
            for (int no = 0; no < NO; no++) {
                const int c0 = no * 8 + (lane & 3) * 2;
                if (lr < cnt)
                    *(__half2*)(partial + (size_t)(start + lr) * COUT + c0) =
                        __floats2half2_rn(acc[mt][no][0], acc[mt][no][1]);
                if (lr + 8 < cnt)
                    *(__half2*)(partial + (size_t)(start + lr + 8) * COUT + c0) =
                        __floats2half2_rn(acc[mt][no][2], acc[mt][no][3]);
            }
        }
        __syncthreads();
    }
}

// ============================================================================
// Phase B: out[row,:] = act( sum_j partial[rowpairs[row][j],:] + bias )
// Each thread handles 16 output columns of one row.
// ============================================================================
template <int COUT, bool RELU, typename OUT_T>
__global__ void __launch_bounds__(256)
phaseB(const __half* __restrict__ partial, const int* __restrict__ rowpairs,
       const int* __restrict__ rcnt, const float* __restrict__ bias,
       OUT_T* __restrict__ out)
{
    constexpr int TPR = COUT / 16;
    const int gid = blockIdx.x * 256 + threadIdx.x;
    const int row = gid / TPR;
    const int q   = gid % TPR;

    float acc[16];
    #pragma unroll
    for (int i = 0; i < 16; i++) acc[i] = bias[q * 16 + i];

    const int cnt = rcnt[row];
    const int* rp = rowpairs + (size_t)row * KOFF;
    for (int j = 0; j < cnt; j++) {
        const int p = rp[j];
        const uint4* pr = (const uint4*)(partial + (size_t)p * COUT + q * 16);
        uint4 u0 = pr[0], u1 = pr[1];
        const uint32_t* u = (const uint32_t*)&u0;
        #pragma unroll
        for (int h = 0; h < 4; h++) {
            float2 f = __half22float2(*(const __half2*)&u[h]);
            acc[h * 2]     += f.x;
            acc[h * 2 + 1] += f.y;
        }
        const uint32_t* v = (const uint32_t*)&u1;
        #pragma unroll
        for (int h = 0; h < 4; h++) {
            float2 f = __half22float2(*(const __half2*)&v[h]);
            acc[8 + h * 2]     += f.x;
            acc[8 + h * 2 + 1] += f.y;
        }
    }
    if (RELU) {
        #pragma unroll
        for (int i = 0; i < 16; i++) acc[i] = fmaxf(acc[i], 0.f);
    }
    if constexpr (sizeof(OUT_T) == 2) {
        __half2 hs[8];
        #pragma unroll
        for (int i = 0; i < 8; i++)
            hs[i] = __floats2half2_rn(acc[2 * i], acc[2 * i + 1]);
        uint4* dst = (uint4*)((__half*)out + (size_t)row * COUT + q * 16);
        dst[0] = *(uint4*)&hs[0];
        dst[1] = *(uint4*)&hs[4];
    } else {
        float4* dst = (float4*)((float*)out + (size_t)row * COUT + q * 16);
        #pragma unroll
        for (int i = 0; i < 4; i++)
            dst[i] = make_float4(acc[4 * i], acc[4 * i + 1],
                                 acc[4 * i + 2], acc[4 * i + 3]);
    }
}

// ============================================================================
// Fused prologue: x -> fp16, and W1/W2/W3 -> mma B-fragment order
// ============================================================================
__device__ __forceinline__ void prep_b_elem(const float* __restrict__ W,
                                            __half* __restrict__ Bf,
                                            int Cout, int i) {
    int NOv  = Cout / 8;
    int lane = i & 31;
    int g    = i >> 5;
    int no   = g % NOv;
    int ko   = (g / NOv) % 4;
    int k    = g / (NOv * 4);
    int n    = no * 8 + (lane >> 2);
    int kk0  = ko * 16 + (lane & 3) * 2;
    const float* Wk = W + (size_t)k * 64 * Cout;
    __half h0 = __float2half_rn(Wk[(kk0 + 0) * Cout + n]);
    __half h1 = __float2half_rn(Wk[(kk0 + 1) * Cout + n]);
    __half h2 = __float2half_rn(Wk[(kk0 + 8) * Cout + n]);
    __half h3 = __float2half_rn(Wk[(kk0 + 9) * Cout + n]);
    uint2 v;
    v.x = (uint32_t)__half_as_ushort(h0) | ((uint32_t)__half_as_ushort(h1) << 16);
    v.y = (uint32_t)__half_as_ushort(h2) | ((uint32_t)__half_as_ushort(h3) << 16);
    ((uint2*)Bf)[i] = v;
}

static constexpr int PREP_NP  = NVOX * CIN / 2;
static constexpr int PREP_T12 = KOFF * 4 * 8 * 32;
static constexpr int PREP_T3  = KOFF * 4 * 2 * 32;
static constexpr int PREP_TOT = PREP_NP + 2 * PREP_T12 + PREP_T3;

__global__ void k_prep(const float* __restrict__ x, __half* __restrict__ xh,
                       const float* __restrict__ W1, __half* __restrict__ w1f,
                       const float* __restrict__ W2, __half* __restrict__ w2f,
                       const float* __restrict__ W3, __half* __restrict__ w3f) {
    int i = blockIdx.x * blockDim.x + threadIdx.x;
    if (i < PREP_NP) {
        float2 v = ((const float2*)x)[i];
        ((__half2*)xh)[i] = __floats2half2_rn(v.x, v.y);
    } else if (i < PREP_NP + PREP_T12) {
        prep_b_elem(W1, w1f, 64, i - PREP_NP);
    } else if (i < PREP_NP + 2 * PREP_T12) {
        prep_b_elem(W2, w2f, 64, i - PREP_NP - PREP_T12);
    } else if (i < PREP_TOT) {
        prep_b_elem(W3, w3f, 16, i - PREP_NP - 2 * PREP_T12);
    }
}

// ============================================================================
// kernel_launch
// ============================================================================
extern "C" void kernel_launch(void* const* d_in, const int* in_sizes, int n_in,
                              void* d_out, int out_size) {
    const float* x    = (const float*)d_in[0];
    const int*   nidx = (const int*)  d_in[1];
    const float* W1   = (const float*)d_in[2];
    const float* b1   = (const float*)d_in[3];
    const float* W2   = (const float*)d_in[4];
    const float* b2   = (const float*)d_in[5];
    const float* W3   = (const float*)d_in[6];
    const float* b3   = (const float*)d_in[7];

    __half *xh, *h1, *h2, *w1f, *w2f, *w3f, *part;
    int *inl, *rp, *rc, *bc, *bb, *ntl;
    int2* tl;
    cudaGetSymbolAddress((void**)&xh,   g_xh);
    cudaGetSymbolAddress((void**)&h1,   g_h1);
    cudaGetSymbolAddress((void**)&h2,   g_h2);
    cudaGetSymbolAddress((void**)&w1f,  g_W1f);
    cudaGetSymbolAddress((void**)&w2f,  g_W2f);
    cudaGetSymbolAddress((void**)&w3f,  g_W3f);
    cudaGetSymbolAddress((void**)&part, g_partial);
    cudaGetSymbolAddress((void**)&inl,  g_inlist);
    cudaGetSymbolAddress((void**)&rp,   g_rowpairs);
    cudaGetSymbolAddress((void**)&rc,   g_rcnt);
    cudaGetSymbolAddress((void**)&bc,   g_blockcnt);
    cudaGetSymbolAddress((void**)&bb,   g_blockbase);
    cudaGetSymbolAddress((void**)&tl,   g_tiles);
    cudaGetSymbolAddress((void**)&ntl,  g_ntiles);

    // pair-list construction + operand prep
    k_prep<<<(PREP_TOT + 255) / 256, 256>>>(x, xh, W1, w1f, W2, w2f, W3, w3f);
    k_count<<<NROWB, NBLK>>>(nidx, bc);
    k_scan<<<1, 256>>>(bc, bb, tl, ntl);
    k_fill<<<NROWB, NBLK>>>(nidx, bb, inl, rp, rc);

    constexpr int SZA64 = TILE * 128 + 64 * 128;   // 40960
    constexpr int SZA16 = TILE * 128 + 16 * 128;   // 34816
    constexpr int GA = 592;                        // persistent phase-A grid

    // layer 1
    phaseA<64><<<GA, 256, SZA64>>>(xh, w1f, inl, tl, ntl, part);
    phaseB<64, true, __half><<<NVOX * 4 / 256, 256>>>(part, rp, rc, b1, h1);
    // layer 2
    phaseA<64><<<GA, 256, SZA64>>>(h1, w2f, inl, tl, ntl, part);
    phaseB<64, true, __half><<<NVOX * 4 / 256, 256>>>(part, rp, rc, b2, h2);
    // layer 3
    phaseA<16><<<GA, 256, SZA16>>>(h2, w3f, inl, tl, ntl, part);
    phaseB<16, false, float><<<NVOX / 256, 256>>>(part, rp, rc, b3,
                                                  (float*)d_out);
}

// round 6
// speedup vs baseline: 1.4038x; 1.0414x over previous
#include <cuda_runtime.h>
#include <cuda_fp16.h>
#include <cstdint>

// ============================================================================
// Problem sizes
// ============================================================================
static constexpr int NVOX  = 65536;
static constexpr int CIN   = 64;
static constexpr int CH    = 64;
static constexpr int COUT3 = 16;
static constexpr int KOFF  = 27;
static constexpr int NBLK  = 256;             // rows per count/fill block
static constexpr int NROWB = NVOX / NBLK;     // 256 blocks
static constexpr int PMAX  = KOFF * NVOX;     // worst-case pair count
static constexpr int TILE  = 256;             // pair rows per phase-A tile
static constexpr int TMAXT = KOFF * (NVOX / TILE);  // worst-case tiles
static constexpr int NWARP = NBLK / 32;       // 8

// ============================================================================
// Device scratch (no dynamic allocation allowed)
// ============================================================================
__device__ __half g_xh[NVOX * CIN];
__device__ __half g_h1[NVOX * CH];
__device__ __half g_h2[NVOX * CH];
__device__ __half g_W1f[KOFF * CH * CIN];
__device__ __half g_W2f[KOFF * CH * CH];
__device__ __half g_W3f[KOFF * COUT3 * CH];

__device__ int    g_inlist[PMAX];                   // input row per pair
__device__ __half g_partial[(size_t)PMAX * 64];     // pair partial rows
__device__ int    g_rowpairs[NVOX * KOFF];          // per-row pair ids
__device__ int    g_rcnt[NVOX];
__device__ int    g_blockcnt[NROWB * KOFF];
__device__ int    g_blockbase[NROWB * KOFF];
__device__ int2   g_tiles[TMAXT];                   // {start, k | cnt<<8}
__device__ int    g_ntiles[1];

// ============================================================================
// PTX helpers
// ============================================================================
__device__ __forceinline__ uint32_t smem_to_u32(const void* smem_ptr) {
    uint32_t addr;
    asm("{ .reg .u64 tmp; cvta.to.shared.u64 tmp, %1; cvt.u32.u64 %0, tmp; }"
        : "=r"(addr) : "l"(smem_ptr));
    return addr;
}
__device__ __forceinline__ void cp_async16(uint32_t dst, const void* src) {
    asm volatile("cp.async.cg.shared.global [%0], [%1], 16;"
                 :: "r"(dst), "l"(src));
}
__device__ __forceinline__ void cp_commit() {
    asm volatile("cp.async.commit_group;");
}
template <int N>
__device__ __forceinline__ void cp_wait() {
    asm volatile("cp.async.wait_group %0;" :: "n"(N));
}
__device__ __forceinline__ void ldmatrix_x4(uint32_t* a, uint32_t addr) {
    asm volatile("ldmatrix.sync.aligned.m8n8.x4.shared.b16 {%0,%1,%2,%3}, [%4];"
                 : "=r"(a[0]), "=r"(a[1]), "=r"(a[2]), "=r"(a[3]) : "r"(addr));
}
__device__ __forceinline__ void mma16816(float* c, const uint32_t* a,
                                         const uint32_t* b) {
    asm volatile(
        "mma.sync.aligned.m16n8k16.row.col.f32.f16.f16.f32 "
        "{%0,%1,%2,%3}, {%4,%5,%6,%7}, {%8,%9}, {%0,%1,%2,%3};"
        : "+f"(c[0]), "+f"(c[1]), "+f"(c[2]), "+f"(c[3])
        : "r"(a[0]), "r"(a[1]), "r"(a[2]), "r"(a[3]), "r"(b[0]), "r"(b[1]));
}

// ============================================================================
// Pair-list construction (deterministic, rebuilt every launch)
// ============================================================================
__global__ void __launch_bounds__(NBLK)
k_count(const int* __restrict__ nidx, int* __restrict__ blockcnt) {
    __shared__ int wcnt[KOFF][NWARP];
    const int t = threadIdx.x, b = blockIdx.x;
    const int w = t >> 5, lane = t & 31;
    const int row = b * NBLK + t;
    const int* ip = nidx + (size_t)row * KOFF;
    unsigned m = 0;
    #pragma unroll
    for (int k = 0; k < KOFF; k++)
        m |= (unsigned)(ip[k] >= 0) << k;
    #pragma unroll
    for (int k = 0; k < KOFF; k++) {
        unsigned bal = __ballot_sync(0xFFFFFFFFu, (m >> k) & 1u);
        if (lane == 0) wcnt[k][w] = __popc(bal);
    }
    __syncthreads();
    if (t < KOFF) {
        int s = 0;
        #pragma unroll
        for (int g = 0; g < NWARP; g++) s += wcnt[t][g];
        blockcnt[b * KOFF + t] = s;
    }
}

__global__ void __launch_bounds__(256)
k_scan(const int* __restrict__ blockcnt, int* __restrict__ blockbase,
       int2* __restrict__ tiles, int* __restrict__ ntiles) {
    constexpr int GB = NROWB / 8;   // 32 blocks per group
    __shared__ int part[KOFF][8];
    __shared__ int cntk[KOFF], kbase[KOFF], tcnt[KOFF], tbase[KOFF];
    const int t = threadIdx.x;
    if (t < KOFF * 8) {
        const int k = t >> 3, g = t & 7;
        int s = 0;
        for (int b = g * GB; b < (g + 1) * GB; b++) s += blockcnt[b * KOFF + k];
        part[k][g] = s;
    }
    __syncthreads();
    if (t < KOFF) {
        int s = 0;
        #pragma unroll
        for (int g = 0; g < 8; g++) s += part[t][g];
        cntk[t] = s;
    }
    __syncthreads();
    if (t == 0) {
        int run = 0, trun = 0;
        for (int k = 0; k < KOFF; k++) {
            kbase[k] = run;  run  += cntk[k];
            tcnt[k]  = (cntk[k] + TILE - 1) / TILE;
            tbase[k] = trun; trun += tcnt[k];
        }
        *ntiles = trun;
    }
    __syncthreads();
    if (t < KOFF * 8) {
        const int k = t >> 3, g = t & 7;
        int run = kbase[k];
        for (int g2 = 0; g2 < g; g2++) run += part[k][g2];
        for (int b = g * GB; b < (g + 1) * GB; b++) {
            blockbase[b * KOFF + k] = run;
            run += blockcnt[b * KOFF + k];
        }
    }
    if (t < KOFF) {
        for (int j = 0; j < tcnt[t]; j++) {
            int st = kbase[t] + j * TILE;
            int c  = min(TILE, cntk[t] - j * TILE);
            tiles[tbase[t] + j] = make_int2(st, t | (c << 8));
        }
    }
}

__global__ void __launch_bounds__(NBLK)
k_fill(const int* __restrict__ nidx, const int* __restrict__ blockbase,
       int* __restrict__ inlist, int* __restrict__ rowpairs,
       int* __restrict__ rcnt) {
    __shared__ int wpre[KOFF][NWARP];
    const int t = threadIdx.x, b = blockIdx.x;
    const int w = t >> 5, lane = t & 31;
    const int row = b * NBLK + t;
    const int* ip = nidx + (size_t)row * KOFF;
    unsigned m = 0;
    #pragma unroll
    for (int k = 0; k < KOFF; k++)
        m |= (unsigned)(ip[k] >= 0) << k;
    #pragma unroll
    for (int k = 0; k < KOFF; k++) {
        unsigned bal = __ballot_sync(0xFFFFFFFFu, (m >> k) & 1u);
        if (lane == 0) wpre[k][w] = __popc(bal);
    }
    __syncthreads();
    if (t < KOFF) {
        int run = 0;
        #pragma unroll
        for (int g = 0; g < NWARP; g++) {
            int c = wpre[t][g];
            wpre[t][g] = run;
            run += c;
        }
    }
    __syncthreads();
    int slot = 0;
    const unsigned lt = (lane == 0) ? 0u : (0xFFFFFFFFu >> (32 - lane));
    #pragma unroll
    for (int k = 0; k < KOFF; k++) {
        const unsigned v = (m >> k) & 1u;
        const unsigned bal = __ballot_sync(0xFFFFFFFFu, v);
        if (v) {
            int p = blockbase[b * KOFF + k] + wpre[k][w] + __popc(bal & lt);
            inlist[p] = ip[k];
            rowpairs[(size_t)row * KOFF + slot] = p;
            slot++;
        }
    }
    rcnt[row] = slot;
}

// ============================================================================
// Phase A: per tile (one k), partial[p,:] = feat[inlist[p],:] @ W[k]
// ============================================================================
template <int COUT>
__global__ void __launch_bounds__(256)
phaseA(const __half* __restrict__ feat, const __half* __restrict__ Wf,
       const int* __restrict__ inlist, const int2* __restrict__ tiles,
       const int* __restrict__ ntiles_p, __half* __restrict__ partial)
{
    constexpr int NO      = COUT / 8;
    constexpr int B_BYTES = COUT * 128;
    constexpr int SMEM_BB = TILE * 128;         // A tile bytes
    extern __shared__ char smem[];
    const uint32_t smem_base = smem_to_u32(smem);
    const int tid  = threadIdx.x;
    const int wid  = tid >> 5;
    const int lane = tid & 31;
    const int nt   = *ntiles_p;
    const int m0   = wid * 32;

    for (int t = blockIdx.x; t < nt; t += gridDim.x) {
        const int2 d   = tiles[t];
        const int start = d.x;
        const int k     = d.y & 31;
        const int cnt   = d.y >> 8;

        // stage B = Wf[k] (fragment-ordered, linear copy)
        {
            const char* bs = (const char*)Wf + (size_t)k * B_BYTES;
            for (int j = tid; j < B_BYTES / 16; j += 256)
                cp_async16(smem_base + SMEM_BB + j * 16, bs + (size_t)j * 16);
        }
        // stage A: thread tid gathers pair row tid of this tile
        if (tid < cnt) {
            int in_row = inlist[start + tid];
            const char* src = (const char*)(feat + (size_t)in_row * 64);
            uint32_t drow = smem_base + tid * 128;
            uint32_t sw = (uint32_t)(tid & 7) * 16;
            #pragma unroll
            for (int c = 0; c < 8; c++)
                cp_async16(drow + (((uint32_t)(c * 16)) ^ sw), src + c * 16);
        }
        cp_commit();
        cp_wait<0>();
        __syncthreads();

        float acc[2][NO][4];
        #pragma unroll
        for (int mt = 0; mt < 2; mt++)
            #pragma unroll
            for (int no = 0; no < NO; no++)
                #pragma unroll
                for (int r = 0; r < 4; r++)
                    acc[mt][no][r] = 0.f;

        #pragma unroll
        for (int ko = 0; ko < 4; ko++) {
            uint32_t afrag[2][4];
            const int ch = ko * 2 + (lane >> 4);
            #pragma unroll
            for (int mt = 0; mt < 2; mt++) {
                int r = m0 + mt * 16 + (lane & 15);
                ldmatrix_x4(afrag[mt],
                    smem_base + r * 128 + (((uint32_t)ch ^ (uint32_t)(r & 7)) * 16));
            }
            #pragma unroll
            for (int no = 0; no < NO; no++) {
                uint32_t b[2];
                asm volatile("ld.shared.v2.b32 {%0,%1}, [%2];"
                             : "=r"(b[0]), "=r"(b[1])
                             : "r"(smem_base + SMEM_BB +
                                   ((ko * NO + no) * 32 + lane) * 8));
                mma16816(acc[0][no], afrag[0], b);
                mma16816(acc[1][no], afrag[1], b);
            }
        }

        // write partial rows (fp16), guarded against tile tail
        #pragma unroll
        for (int mt = 0; mt < 2; mt++) {
            const int lr = m0 + mt * 16 + (lane >> 2);
            #pragma unroll
            for (int no = 0; no < NO; no++) {
                const int c0 = no * 8 + (lane & 3) * 2;
                if (lr < cnt)
                    *(__half2*)(partial + (size_t)(start + lr) * COUT + c0) =
                        __floats2half2_rn(acc[mt][no][0], acc[mt][no][1]);
                if (lr + 8 < cnt)
                    *(__half2*)(partial + (size_t)(start + lr + 8) * COUT + c0) =
                        __floats2half2_rn(acc[mt][no][2], acc[mt][no][3]);
            }
        }
        __syncthreads();
    }
}

// ============================================================================
// Phase B: out[row,:] = act( sum_j partial[rowpairs[row][j],:] + bias )
// ============================================================================
template <int COUT, bool RELU, typename OUT_T>
__global__ void __launch_bounds__(256)
phaseB(const __half* __restrict__ partial, const int* __restrict__ rowpairs,
       const int* __restrict__ rcnt, const float* __restrict__ bias,
       OUT_T* __restrict__ out)
{
    constexpr int TPR = COUT / 16;
    const int gid = blockIdx.x * 256 + threadIdx.x;
    const int row = gid / TPR;
    const int q   = gid % TPR;

    float acc[16];
    #pragma unroll
    for (int i = 0; i < 16; i++) acc[i] = bias[q * 16 + i];

    const int cnt = rcnt[row];
    const int* rp = rowpairs + (size_t)row * KOFF;
    for (int j = 0; j < cnt; j++) {
        const int p = rp[j];
        const uint4* pr = (const uint4*)(partial + (size_t)p * COUT + q * 16);
        uint4 u0 = pr[0], u1 = pr[1];
        const uint32_t* u = (const uint32_t*)&u0;
        #pragma unroll
        for (int h = 0; h < 4; h++) {
            float2 f = __half22float2(*(const __half2*)&u[h]);
            acc[h * 2]     += f.x;
            acc[h * 2 + 1] += f.y;
        }
        const uint32_t* v = (const uint32_t*)&u1;
        #pragma unroll
        for (int h = 0; h < 4; h++) {
            float2 f = __half22float2(*(const __half2*)&v[h]);
            acc[8 + h * 2]     += f.x;
            acc[8 + h * 2 + 1] += f.y;
        }
    }
    if (RELU) {
        #pragma unroll
        for (int i = 0; i < 16; i++) acc[i] = fmaxf(acc[i], 0.f);
    }
    if constexpr (sizeof(OUT_T) == 2) {
        __half2 hs[8];
        #pragma unroll
        for (int i = 0; i < 8; i++)
            hs[i] = __floats2half2_rn(acc[2 * i], acc[2 * i + 1]);
        uint4* dst = (uint4*)((__half*)out + (size_t)row * COUT + q * 16);
        dst[0] = *(uint4*)&hs[0];
        dst[1] = *(uint4*)&hs[4];
    } else {
        float4* dst = (float4*)((float*)out + (size_t)row * COUT + q * 16);
        #pragma unroll
        for (int i = 0; i < 4; i++)
            dst[i] = make_float4(acc[4 * i], acc[4 * i + 1],
                                 acc[4 * i + 2], acc[4 * i + 3]);
    }
}

// ============================================================================
// Fused prologue: x -> fp16, and W1/W2/W3 -> mma B-fragment order
// ============================================================================
__device__ __forceinline__ void prep_b_elem(const float* __restrict__ W,
                                            __half* __restrict__ Bf,
                                            int Cout, int i) {
    int NOv  = Cout / 8;
    int lane = i & 31;
    int g    = i >> 5;
    int no   = g % NOv;
    int ko   = (g / NOv) % 4;
    int k    = g / (NOv * 4);
    int n    = no * 8 + (lane >> 2);
    int kk0  = ko * 16 + (lane & 3) * 2;
    const float* Wk = W + (size_t)k * 64 * Cout;
    __half h0 = __float2half_rn(Wk[(kk0 + 0) * Cout + n]);
    __half h1 = __float2half_rn(Wk[(kk0 + 1) * Cout + n]);
    __half h2 = __float2half_rn(Wk[(kk0 + 8) * Cout + n]);
    __half h3 = __float2half_rn(Wk[(kk0 + 9) * Cout + n]);
    uint2 v;
    v.x = (uint32_t)__half_as_ushort(h0) | ((uint32_t)__half_as_ushort(h1) << 16);
    v.y = (uint32_t)__half_as_ushort(h2) | ((uint32_t)__half_as_ushort(h3) << 16);
    ((uint2*)Bf)[i] = v;
}

static constexpr int PREP_NP  = NVOX * CIN / 2;
static constexpr int PREP_T12 = KOFF * 4 * 8 * 32;
static constexpr int PREP_T3  = KOFF * 4 * 2 * 32;
static constexpr int PREP_TOT = PREP_NP + 2 * PREP_T12 + PREP_T3;

__global__ void k_prep(const float* __restrict__ x, __half* __restrict__ xh,
                       const float* __restrict__ W1, __half* __restrict__ w1f,
                       const float* __restrict__ W2, __half* __restrict__ w2f,
                       const float* __restrict__ W3, __half* __restrict__ w3f) {
    int i = blockIdx.x * blockDim.x + threadIdx.x;
    if (i < PREP_NP) {
        float2 v = ((const float2*)x)[i];
        ((__half2*)xh)[i] = __floats2half2_rn(v.x, v.y);
    } else if (i < PREP_NP + PREP_T12) {
        prep_b_elem(W1, w1f, 64, i - PREP_NP);
    } else if (i < PREP_NP + 2 * PREP_T12) {
        prep_b_elem(W2, w2f, 64, i - PREP_NP - PREP_T12);
    } else if (i < PREP_TOT) {
        prep_b_elem(W3, w3f, 16, i - PREP_NP - 2 * PREP_T12);
    }
}

// ============================================================================
// kernel_launch
// ============================================================================
extern "C" void kernel_launch(void* const* d_in, const int* in_sizes, int n_in,
                              void* d_out, int out_size) {
    const float* x    = (const float*)d_in[0];
    const int*   nidx = (const int*)  d_in[1];
    const float* W1   = (const float*)d_in[2];
    const float* b1   = (const float*)d_in[3];
    const float* W2   = (const float*)d_in[4];
    const float* b2   = (const float*)d_in[5];
    const float* W3   = (const float*)d_in[6];
    const float* b3   = (const float*)d_in[7];

    __half *xh, *h1, *h2, *w1f, *w2f, *w3f, *part;
    int *inl, *rp, *rc, *bc, *bb, *ntl;
    int2* tl;
    cudaGetSymbolAddress((void**)&xh,   g_xh);
    cudaGetSymbolAddress((void**)&h1,   g_h1);
    cudaGetSymbolAddress((void**)&h2,   g_h2);
    cudaGetSymbolAddress((void**)&w1f,  g_W1f);
    cudaGetSymbolAddress((void**)&w2f,  g_W2f);
    cudaGetSymbolAddress((void**)&w3f,  g_W3f);
    cudaGetSymbolAddress((void**)&part, g_partial);
    cudaGetSymbolAddress((void**)&inl,  g_inlist);
    cudaGetSymbolAddress((void**)&rp,   g_rowpairs);
    cudaGetSymbolAddress((void**)&rc,   g_rcnt);
    cudaGetSymbolAddress((void**)&bc,   g_blockcnt);
    cudaGetSymbolAddress((void**)&bb,   g_blockbase);
    cudaGetSymbolAddress((void**)&tl,   g_tiles);
    cudaGetSymbolAddress((void**)&ntl,  g_ntiles);

    // ---- fork: pair-list branch (reads only nidx) runs parallel to k_prep ----
    cudaStream_t s1;
    cudaStreamCreateWithFlags(&s1, cudaStreamNonBlocking);
    cudaEvent_t e0, e1;
    cudaEventCreateWithFlags(&e0, cudaEventDisableTiming);
    cudaEventCreateWithFlags(&e1, cudaEventDisableTiming);

    cudaEventRecord(e0, 0);
    cudaStreamWaitEvent(s1, e0, 0);

    k_prep<<<(PREP_TOT + 255) / 256, 256>>>(x, xh, W1, w1f, W2, w2f, W3, w3f);

    k_count<<<NROWB, NBLK, 0, s1>>>(nidx, bc);
    k_scan<<<1, 256, 0, s1>>>(bc, bb, tl, ntl);
    k_fill<<<NROWB, NBLK, 0, s1>>>(nidx, bb, inl, rp, rc);

    cudaEventRecord(e1, s1);
    cudaStreamWaitEvent(0, e1, 0);

    constexpr int SZA64 = TILE * 128 + 64 * 128;   // 40960
    constexpr int SZA16 = TILE * 128 + 16 * 128;   // 34816
    constexpr int GA = 592;                        // persistent phase-A grid

    // layer 1
    phaseA<64><<<GA, 256, SZA64>>>(xh, w1f, inl, tl, ntl, part);
    phaseB<64, true, __half><<<NVOX * 4 / 256, 256>>>(part, rp, rc, b1, h1);
    // layer 2
    phaseA<64><<<GA, 256, SZA64>>>(h1, w2f, inl, tl, ntl, part);
    phaseB<64, true, __half><<<NVOX * 4 / 256, 256>>>(part, rp, rc, b2, h2);
    // layer 3
    phaseA<16><<<GA, 256, SZA16>>>(h2, w3f, inl, tl, ntl, part);
    phaseB<16, false, float><<<NVOX / 256, 256>>>(part, rp, rc, b3,
                                                  (float*)d_out);

    cudaEventDestroy(e0);
    cudaEventDestroy(e1);
    cudaStreamDestroy(s1);
}

// round 7
// speedup vs baseline: 1.4731x; 1.0494x over previous
#include <cuda_runtime.h>
#include <cuda_fp16.h>
#include <cstdint>

// ============================================================================
// Problem sizes
// ============================================================================
static constexpr int NVOX  = 65536;
static constexpr int CIN   = 64;
static constexpr int CH    = 64;
static constexpr int COUT3 = 16;
static constexpr int KOFF  = 27;
static constexpr int NBLK  = 256;             // rows per fill block
static constexpr int NROWB = NVOX / NBLK;     // 256 blocks
static constexpr int PMAX  = KOFF * NVOX;     // fixed per-k segments of NVOX
static constexpr int TILE  = 256;             // pair rows per phase-A tile
static constexpr int TMAXT = KOFF * (NVOX / TILE);
static constexpr int NWARP = NBLK / 32;       // 8

// ============================================================================
// Device scratch (no dynamic allocation allowed)
// ============================================================================
__device__ __half g_xh[NVOX * CIN];
__device__ __half g_h1[NVOX * CH];
__device__ __half g_h2[NVOX * CH];
__device__ __half g_W1f[KOFF * CH * CIN];
__device__ __half g_W2f[KOFF * CH * CH];
__device__ __half g_W3f[KOFF * COUT3 * CH];

__device__ int    g_inlist[PMAX];                   // input row per pair
__device__ __half g_partial[(size_t)PMAX * 64];     // pair partial rows
__device__ int    g_rowpairs[NVOX * KOFF];          // per-row pair ids
__device__ int    g_rcnt[NVOX];
__device__ int    g_kcnt[KOFF];                     // pairs per offset
__device__ int2   g_tiles[TMAXT];                   // {start, k | cnt<<8}
__device__ int    g_ntiles[1];

// ============================================================================
// PTX helpers
// ============================================================================
__device__ __forceinline__ uint32_t smem_to_u32(const void* smem_ptr) {
    uint32_t addr;
    asm("{ .reg .u64 tmp; cvta.to.shared.u64 tmp, %1; cvt.u32.u64 %0, tmp; }"
        : "=r"(addr) : "l"(smem_ptr));
    return addr;
}
__device__ __forceinline__ void cp_async16(uint32_t dst, const void* src) {
    asm volatile("cp.async.cg.shared.global [%0], [%1], 16;"
                 :: "r"(dst), "l"(src));
}
__device__ __forceinline__ void cp_commit() {
    asm volatile("cp.async.commit_group;");
}
template <int N>
__device__ __forceinline__ void cp_wait() {
    asm volatile("cp.async.wait_group %0;" :: "n"(N));
}
__device__ __forceinline__ void ldmatrix_x4(uint32_t* a, uint32_t addr) {
    asm volatile("ldmatrix.sync.aligned.m8n8.x4.shared.b16 {%0,%1,%2,%3}, [%4];"
                 : "=r"(a[0]), "=r"(a[1]), "=r"(a[2]), "=r"(a[3]) : "r"(addr));
}
__device__ __forceinline__ void mma16816(float* c, const uint32_t* a,
                                         const uint32_t* b) {
    asm volatile(
        "mma.sync.aligned.m16n8k16.row.col.f32.f16.f16.f32 "
        "{%0,%1,%2,%3}, {%4,%5,%6,%7}, {%8,%9}, {%0,%1,%2,%3};"
        : "+f"(c[0]), "+f"(c[1]), "+f"(c[2]), "+f"(c[3])
        : "r"(a[0]), "r"(a[1]), "r"(a[2]), "r"(a[3]), "r"(b[0]), "r"(b[1]));
}

// ============================================================================
// Pair-list construction: ONE pass over nidx. Pairs for offset k land in the
// fixed segment [k*NVOX, k*NVOX + kcnt[k]) via block-aggregated atomicAdd.
// Placement order is nondeterministic but output-invariant: partial[p]
// depends only on (inlist[p], k), and phaseB sums in fixed slot order.
// ============================================================================
__global__ void __launch_bounds__(NBLK)
k_fill(const int* __restrict__ nidx, int* __restrict__ kcnt,
       int* __restrict__ inlist, int* __restrict__ rowpairs,
       int* __restrict__ rcnt) {
    __shared__ int wpre[KOFF][NWARP];
    __shared__ int kbase[KOFF];
    const int t = threadIdx.x, b = blockIdx.x;
    const int w = t >> 5, lane = t & 31;
    const int row = b * NBLK + t;
    const int* ip = nidx + (size_t)row * KOFF;
    unsigned m = 0;
    #pragma unroll
    for (int k = 0; k < KOFF; k++)
        m |= (unsigned)(ip[k] >= 0) << k;
    #pragma unroll
    for (int k = 0; k < KOFF; k++) {
        unsigned bal = __ballot_sync(0xFFFFFFFFu, (m >> k) & 1u);
        if (lane == 0) wpre[k][w] = __popc(bal);
    }
    __syncthreads();
    if (t < KOFF) {
        int run = 0;
        #pragma unroll
        for (int g = 0; g < NWARP; g++) {
            int c = wpre[t][g];
            wpre[t][g] = run;
            run += c;
        }
        kbase[t] = atomicAdd(&kcnt[t], run);
    }
    __syncthreads();
    int slot = 0;
    const unsigned lt = (lane == 0) ? 0u : (0xFFFFFFFFu >> (32 - lane));
    #pragma unroll
    for (int k = 0; k < KOFF; k++) {
        const unsigned v = (m >> k) & 1u;
        const unsigned bal = __ballot_sync(0xFFFFFFFFu, v);
        if (v) {
            int p = k * NVOX + kbase[k] + wpre[k][w] + __popc(bal & lt);
            inlist[p] = ip[k];
            rowpairs[(size_t)row * KOFF + slot] = p;
            slot++;
        }
    }
    rcnt[row] = slot;
}

__global__ void k_tiles(const int* __restrict__ kcnt, int2* __restrict__ tiles,
                        int* __restrict__ ntiles) {
    __shared__ int tc[KOFF], tb[KOFF];
    const int t = threadIdx.x;
    if (t < KOFF) tc[t] = (kcnt[t] + TILE - 1) / TILE;
    __syncthreads();
    if (t == 0) {
        int run = 0;
        for (int k = 0; k < KOFF; k++) { tb[k] = run; run += tc[k]; }
        *ntiles = run;
    }
    __syncthreads();
    if (t < KOFF) {
        const int cnt = kcnt[t];
        for (int j = 0; j < tc[t]; j++)
            tiles[tb[t] + j] = make_int2(t * NVOX + j * TILE,
                                         t | (min(TILE, cnt - j * TILE) << 8));
    }
}

// ============================================================================
// Phase A (double-buffered): per tile (one k),
//   partial[p,:] = feat[inlist[p],:] @ W[k]
// ============================================================================
template <int COUT>
__global__ void __launch_bounds__(256)
phaseA(const __half* __restrict__ feat, const __half* __restrict__ Wf,
       const int* __restrict__ inlist, const int2* __restrict__ tiles,
       const int* __restrict__ ntiles_p, __half* __restrict__ partial)
{
    constexpr int NO       = COUT / 8;
    constexpr int B_BYTES  = COUT * 128;
    constexpr int A_BYTES  = TILE * 128;
    constexpr int BUF      = A_BYTES + B_BYTES;
    extern __shared__ char smem[];
    const uint32_t smem_base = smem_to_u32(smem);
    const int tid  = threadIdx.x;
    const int wid  = tid >> 5;
    const int lane = tid & 31;
    const int nt   = *ntiles_p;
    const int m0   = wid * 32;

    // stage tile t into buffer buf (A rows + this k's B tile), then commit
    auto stage = [&](int t, int buf) {
        const int2 d = tiles[t];
        const int start = d.x;
        const int k     = d.y & 31;
        const int cnt   = d.y >> 8;
        const char* bs = (const char*)Wf + (size_t)k * B_BYTES;
        const uint32_t base = smem_base + buf * BUF;
        for (int j = tid; j < B_BYTES / 16; j += 256)
            cp_async16(base + A_BYTES + j * 16, bs + (size_t)j * 16);
        if (tid < cnt) {
            int in_row = inlist[start + tid];
            const char* src = (const char*)(feat + (size_t)in_row * 64);
            uint32_t drow = base + tid * 128;
            uint32_t sw = (uint32_t)(tid & 7) * 16;
            #pragma unroll
            for (int c = 0; c < 8; c++)
                cp_async16(drow + (((uint32_t)(c * 16)) ^ sw), src + c * 16);
        }
        cp_commit();
    };

    int t = blockIdx.x;
    if (t < nt) stage(t, 0);
    int buf = 0;

    for (; t < nt; t += gridDim.x) {
        const int tn = t + gridDim.x;
        if (tn < nt) { stage(tn, buf ^ 1); cp_wait<1>(); }
        else         { cp_wait<0>(); }
        __syncthreads();

        const int2 d = tiles[t];
        const int start = d.x;
        const int cnt   = d.y >> 8;
        const uint32_t aBase = smem_base + buf * BUF;
        const uint32_t bBase = aBase + A_BYTES;

        float acc[2][NO][4];
        #pragma unroll
        for (int mt = 0; mt < 2; mt++)
            #pragma unroll
            for (int no = 0; no < NO; no++)
                #pragma unroll
                for (int r = 0; r < 4; r++)
                    acc[mt][no][r] = 0.f;

        #pragma unroll
        for (int ko = 0; ko < 4; ko++) {
            uint32_t afrag[2][4];
            const int ch = ko * 2 + (lane >> 4);
            #pragma unroll
            for (int mt = 0; mt < 2; mt++) {
                int r = m0 + mt * 16 + (lane & 15);
                ldmatrix_x4(afrag[mt],
                    aBase + r * 128 + (((uint32_t)ch ^ (uint32_t)(r & 7)) * 16));
            }
            #pragma unroll
            for (int no = 0; no < NO; no++) {
                uint32_t b[2];
                asm volatile("ld.shared.v2.b32 {%0,%1}, [%2];"
                             : "=r"(b[0]), "=r"(b[1])
                             : "r"(bBase + ((ko * NO + no) * 32 + lane) * 8));
                mma16816(acc[0][no], afrag[0], b);
                mma16816(acc[1][no], afrag[1], b);
            }
        }

        // write partial rows (fp16), guarded against tile tail
        #pragma unroll
        for (int mt = 0; mt < 2; mt++) {
            const int lr = m0 + mt * 16 + (lane >> 2);
            #pragma unroll
            for (int no = 0; no < NO; no++) {
                const int c0 = no * 8 + (lane & 3) * 2;
                if (lr < cnt)
                    *(__half2*)(partial + (size_t)(start + lr) * COUT + c0) =
                        __floats2half2_rn(acc[mt][no][0], acc[mt][no][1]);
                if (lr + 8 < cnt)
                    *(__half2*)(partial + (size_t)(start + lr + 8) * COUT + c0) =
                        __floats2half2_rn(acc[mt][no][2], acc[mt][no][3]);
            }
        }
        __syncthreads();
        buf ^= 1;
    }
}

// ============================================================================
// Phase B: out[row,:] = act( sum_j partial[rowpairs[row][j],:] + bias )
// ============================================================================
template <int COUT, bool RELU, typename OUT_T>
__global__ void __launch_bounds__(256)
phaseB(const __half* __restrict__ partial, const int* __restrict__ rowpairs,
       const int* __restrict__ rcnt, const float* __restrict__ bias,
       OUT_T* __restrict__ out)
{
    constexpr int TPR = COUT / 16;
    const int gid = blockIdx.x * 256 + threadIdx.x;
    const int row = gid / TPR;
    const int q   = gid % TPR;

    float acc[16];
    #pragma unroll
    for (int i = 0; i < 16; i++) acc[i] = bias[q * 16 + i];

    const int cnt = rcnt[row];
    const int* rp = rowpairs + (size_t)row * KOFF;
    for (int j = 0; j < cnt; j++) {
        const int p = rp[j];
        const uint4* pr = (const uint4*)(partial + (size_t)p * COUT + q * 16);
        uint4 u0 = pr[0], u1 = pr[1];
        const uint32_t* u = (const uint32_t*)&u0;
        #pragma unroll
        for (int h = 0; h < 4; h++) {
            float2 f = __half22float2(*(const __half2*)&u[h]);
            acc[h * 2]     += f.x;
            acc[h * 2 + 1] += f.y;
        }
        const uint32_t* v = (const uint32_t*)&u1;
        #pragma unroll
        for (int h = 0; h < 4; h++) {
            float2 f = __half22float2(*(const __half2*)&v[h]);
            acc[8 + h * 2]     += f.x;
            acc[8 + h * 2 + 1] += f.y;
        }
    }
    if (RELU) {
        #pragma unroll
        for (int i = 0; i < 16; i++) acc[i] = fmaxf(acc[i], 0.f);
    }
    if constexpr (sizeof(OUT_T) == 2) {
        __half2 hs[8];
        #pragma unroll
        for (int i = 0; i < 8; i++)
            hs[i] = __floats2half2_rn(acc[2 * i], acc[2 * i + 1]);
        uint4* dst = (uint4*)((__half*)out + (size_t)row * COUT + q * 16);
        dst[0] = *(uint4*)&hs[0];
        dst[1] = *(uint4*)&hs[4];
    } else {
        float4* dst = (float4*)((float*)out + (size_t)row * COUT + q * 16);
        #pragma unroll
        for (int i = 0; i < 4; i++)
            dst[i] = make_float4(acc[4 * i], acc[4 * i + 1],
                                 acc[4 * i + 2], acc[4 * i + 3]);
    }
}

// ============================================================================
// Fused prologue: x -> fp16, and W1/W2/W3 -> mma B-fragment order
// ============================================================================
__device__ __forceinline__ void prep_b_elem(const float* __restrict__ W,
                                            __half* __restrict__ Bf,
                                            int Cout, int i) {
    int NOv  = Cout / 8;
    int lane = i & 31;
    int g    = i >> 5;
    int no   = g % NOv;
    int ko   = (g / NOv) % 4;
    int k    = g / (NOv * 4);
    int n    = no * 8 + (lane >> 2);
    int kk0  = ko * 16 + (lane & 3) * 2;
    const float* Wk = W + (size_t)k * 64 * Cout;
    __half h0 = __float2half_rn(Wk[(kk0 + 0) * Cout + n]);
    __half h1 = __float2half_rn(Wk[(kk0 + 1) * Cout + n]);
    __half h2 = __float2half_rn(Wk[(kk0 + 8) * Cout + n]);
    __half h3 = __float2half_rn(Wk[(kk0 + 9) * Cout + n]);
    uint2 v;
    v.x = (uint32_t)__half_as_ushort(h0) | ((uint32_t)__half_as_ushort(h1) << 16);
    v.y = (uint32_t)__half_as_ushort(h2) | ((uint32_t)__half_as_ushort(h3) << 16);
    ((uint2*)Bf)[i] = v;
}

static constexpr int PREP_NP  = NVOX * CIN / 2;
static constexpr int PREP_T12 = KOFF * 4 * 8 * 32;
static constexpr int PREP_T3  = KOFF * 4 * 2 * 32;
static constexpr int PREP_TOT = PREP_NP + 2 * PREP_T12 + PREP_T3;

__global__ void k_prep(const float* __restrict__ x, __half* __restrict__ xh,
                       const float* __restrict__ W1, __half* __restrict__ w1f,
                       const float* __restrict__ W2, __half* __restrict__ w2f,
                       const float* __restrict__ W3, __half* __restrict__ w3f) {
    int i = blockIdx.x * blockDim.x + threadIdx.x;
    if (i < PREP_NP) {
        float2 v = ((const float2*)x)[i];
        ((__half2*)xh)[i] = __floats2half2_rn(v.x, v.y);
    } else if (i < PREP_NP + PREP_T12) {
        prep_b_elem(W1, w1f, 64, i - PREP_NP);
    } else if (i < PREP_NP + 2 * PREP_T12) {
        prep_b_elem(W2, w2f, 64, i - PREP_NP - PREP_T12);
    } else if (i < PREP_TOT) {
        prep_b_elem(W3, w3f, 16, i - PREP_NP - 2 * PREP_T12);
    }
}

// ============================================================================
// kernel_launch
// ============================================================================
extern "C" void kernel_launch(void* const* d_in, const int* in_sizes, int n_in,
                              void* d_out, int out_size) {
    const float* x    = (const float*)d_in[0];
    const int*   nidx = (const int*)  d_in[1];
    const float* W1   = (const float*)d_in[2];
    const float* b1   = (const float*)d_in[3];
    const float* W2   = (const float*)d_in[4];
    const float* b2   = (const float*)d_in[5];
    const float* W3   = (const float*)d_in[6];
    const float* b3   = (const float*)d_in[7];

    __half *xh, *h1, *h2, *w1f, *w2f, *w3f, *part;
    int *inl, *rp, *rc, *kc, *ntl;
    int2* tl;
    cudaGetSymbolAddress((void**)&xh,   g_xh);
    cudaGetSymbolAddress((void**)&h1,   g_h1);
    cudaGetSymbolAddress((void**)&h2,   g_h2);
    cudaGetSymbolAddress((void**)&w1f,  g_W1f);
    cudaGetSymbolAddress((void**)&w2f,  g_W2f);
    cudaGetSymbolAddress((void**)&w3f,  g_W3f);
    cudaGetSymbolAddress((void**)&part, g_partial);
    cudaGetSymbolAddress((void**)&inl,  g_inlist);
    cudaGetSymbolAddress((void**)&rp,   g_rowpairs);
    cudaGetSymbolAddress((void**)&rc,   g_rcnt);
    cudaGetSymbolAddress((void**)&kc,   g_kcnt);
    cudaGetSymbolAddress((void**)&tl,   g_tiles);
    cudaGetSymbolAddress((void**)&ntl,  g_ntiles);

    // ---- fork: pair-list branch (reads only nidx) runs parallel to k_prep ----
    cudaStream_t s1;
    cudaStreamCreateWithFlags(&s1, cudaStreamNonBlocking);
    cudaEvent_t e0, e1;
    cudaEventCreateWithFlags(&e0, cudaEventDisableTiming);
    cudaEventCreateWithFlags(&e1, cudaEventDisableTiming);

    cudaEventRecord(e0, 0);
    cudaStreamWaitEvent(s1, e0, 0);

    k_prep<<<(PREP_TOT + 255) / 256, 256>>>(x, xh, W1, w1f, W2, w2f, W3, w3f);

    cudaMemsetAsync(kc, 0, KOFF * sizeof(int), s1);
    k_fill<<<NROWB, NBLK, 0, s1>>>(nidx, kc, inl, rp, rc);
    k_tiles<<<1, 32, 0, s1>>>(kc, tl, ntl);

    cudaEventRecord(e1, s1);
    cudaStreamWaitEvent(0, e1, 0);

    constexpr int SZA64 = 2 * (TILE * 128 + 64 * 128);  // 81920
    constexpr int SZA16 = 2 * (TILE * 128 + 16 * 128);  // 69632
    constexpr int GA = 296;                             // 2 CTAs/SM persistent
    cudaFuncSetAttribute((const void*)phaseA<64>,
                         cudaFuncAttributeMaxDynamicSharedMemorySize, SZA64);
    cudaFuncSetAttribute((const void*)phaseA<16>,
                         cudaFuncAttributeMaxDynamicSharedMemorySize, SZA16);

    // layer 1
    phaseA<64><<<GA, 256, SZA64>>>(xh, w1f, inl, tl, ntl, part);
    phaseB<64, true, __half><<<NVOX * 4 / 256, 256>>>(part, rp, rc, b1, h1);
    // layer 2
    phaseA<64><<<GA, 256, SZA64>>>(h1, w2f, inl, tl, ntl, part);
    phaseB<64, true, __half><<<NVOX * 4 / 256, 256>>>(part, rp, rc, b2, h2);
    // layer 3
    phaseA<16><<<GA, 256, SZA16>>>(h2, w3f, inl, tl, ntl, part);
    phaseB<16, false, float><<<NVOX / 256, 256>>>(part, rp, rc, b3,
                                                  (float*)d_out);

    cudaEventDestroy(e0);
    cudaEventDestroy(e1);
    cudaStreamDestroy(s1);
}

// round 10
// speedup vs baseline: 1.6934x; 1.1495x over previous
#include <cuda_runtime.h>
#include <cuda_fp16.h>
#include <cstdint>

// ============================================================================
// Problem sizes
// ============================================================================
static constexpr int NVOX  = 65536;
static constexpr int CIN   = 64;
static constexpr int CH    = 64;
static constexpr int COUT3 = 16;
static constexpr int KOFF  = 27;
static constexpr int NBLK  = 256;             // rows per fill block
static constexpr int NROWB = NVOX / NBLK;     // 256 blocks
static constexpr int PMAX  = KOFF * NVOX;     // fixed per-k segments of NVOX
static constexpr int TILE  = 256;             // pair rows per phase-A tile
static constexpr int TMAXT = KOFF * (NVOX / TILE);
static constexpr int NWARP = NBLK / 32;       // 8

// ============================================================================
// Device scratch (no dynamic allocation allowed)
// ============================================================================
__device__ __half g_xh[NVOX * CIN];
__device__ __half g_h1[NVOX * CH];
__device__ __half g_h2[NVOX * CH];
__device__ __half g_W1f[KOFF * CH * CIN];
__device__ __half g_W2f[KOFF * CH * CH];
__device__ __half g_W3f[KOFF * COUT3 * CH];

__device__ int    g_inlist[PMAX];                   // input row per pair
__device__ __half g_partial[(size_t)PMAX * 64];     // pair partial rows
__device__ int    g_rowpairs[NVOX * KOFF];          // per-row pair ids
__device__ int    g_rcnt[NVOX];
__device__ int    g_kcnt[KOFF];                     // pairs per offset
__device__ int2   g_tiles[TMAXT];                   // {start, k | cnt<<8}
__device__ int    g_ntiles[1];

// ============================================================================
// PTX helpers
// ============================================================================
__device__ __forceinline__ uint32_t smem_to_u32(const void* smem_ptr) {
    uint32_t addr;
    asm("{ .reg .u64 tmp; cvta.to.shared.u64 tmp, %1; cvt.u32.u64 %0, tmp; }"
        : "=r"(addr) : "l"(smem_ptr));
    return addr;
}
__device__ __forceinline__ void cp_async16(uint32_t dst, const void* src) {
    asm volatile("cp.async.cg.shared.global [%0], [%1], 16;"
                 :: "r"(dst), "l"(src));
}
__device__ __forceinline__ void cp_commit() {
    asm volatile("cp.async.commit_group;");
}
template <int N>
__device__ __forceinline__ void cp_wait() {
    asm volatile("cp.async.wait_group %0;" :: "n"(N));
}
__device__ __forceinline__ void ldmatrix_x4(uint32_t* a, uint32_t addr) {
    asm volatile("ldmatrix.sync.aligned.m8n8.x4.shared.b16 {%0,%1,%2,%3}, [%4];"
                 : "=r"(a[0]), "=r"(a[1]), "=r"(a[2]), "=r"(a[3]) : "r"(addr));
}
__device__ __forceinline__ void mma16816(float* c, const uint32_t* a,
                                         const uint32_t* b) {
    asm volatile(
        "mma.sync.aligned.m16n8k16.row.col.f32.f16.f16.f32 "
        "{%0,%1,%2,%3}, {%4,%5,%6,%7}, {%8,%9}, {%0,%1,%2,%3};"
        : "+f"(c[0]), "+f"(c[1]), "+f"(c[2]), "+f"(c[3])
        : "r"(a[0]), "r"(a[1]), "r"(a[2]), "r"(a[3]), "r"(b[0]), "r"(b[1]));
}

// ============================================================================
// Pair-list construction: ONE pass over nidx. Pairs for offset k land in the
// fixed segment [k*NVOX, ...) via block-aggregated atomicAdd. Placement order
// is nondeterministic but output-invariant (partial[p] depends only on
// (inlist[p], k); phaseB sums in fixed slot order).
// ============================================================================
__global__ void __launch_bounds__(NBLK)
k_fill(const int* __restrict__ nidx, int* __restrict__ kcnt,
       int* __restrict__ inlist, int* __restrict__ rowpairs,
       int* __restrict__ rcnt) {
    __shared__ int wpre[KOFF][NWARP];
    __shared__ int kbase[KOFF];
    const int t = threadIdx.x, b = blockIdx.x;
    const int w = t >> 5, lane = t & 31;
    const int row = b * NBLK + t;
    const int* ip = nidx + (size_t)row * KOFF;
    unsigned m = 0;
    #pragma unroll
    for (int k = 0; k < KOFF; k++)
        m |= (unsigned)(ip[k] >= 0) << k;
    #pragma unroll
    for (int k = 0; k < KOFF; k++) {
        unsigned bal = __ballot_sync(0xFFFFFFFFu, (m >> k) & 1u);
        if (lane == 0) wpre[k][w] = __popc(bal);
    }
    __syncthreads();
    if (t < KOFF) {
        int run = 0;
        #pragma unroll
        for (int g = 0; g < NWARP; g++) {
            int c = wpre[t][g];
            wpre[t][g] = run;
            run += c;
        }
        kbase[t] = atomicAdd(&kcnt[t], run);
    }
    __syncthreads();
    int slot = 0;
    const unsigned lt = (lane == 0) ? 0u : (0xFFFFFFFFu >> (32 - lane));
    #pragma unroll
    for (int k = 0; k < KOFF; k++) {
        const unsigned v = (m >> k) & 1u;
        const unsigned bal = __ballot_sync(0xFFFFFFFFu, v);
        if (v) {
            int p = k * NVOX + kbase[k] + wpre[k][w] + __popc(bal & lt);
            inlist[p] = ip[k];
            rowpairs[(size_t)row * KOFF + slot] = p;
            slot++;
        }
    }
    rcnt[row] = slot;
}

__global__ void k_tiles(const int* __restrict__ kcnt, int2* __restrict__ tiles,
                        int* __restrict__ ntiles) {
    __shared__ int tc[KOFF], tb[KOFF];
    const int t = threadIdx.x;
    if (t < KOFF) tc[t] = (kcnt[t] + TILE - 1) / TILE;
    __syncthreads();
    if (t == 0) {
        int run = 0;
        for (int k = 0; k < KOFF; k++) { tb[k] = run; run += tc[k]; }
        *ntiles = run;
    }
    __syncthreads();
    if (t < KOFF) {
        const int cnt = kcnt[t];
        for (int j = 0; j < tc[t]; j++)
            tiles[tb[t] + j] = make_int2(t * NVOX + j * TILE,
                                         t | (min(TILE, cnt - j * TILE) << 8));
    }
}

// ============================================================================
// Phase A (double-buffered): per tile (one k),
//   partial[p,:] = feat[inlist[p],:] @ W[k]
// Gather is coalesced: 8 consecutive lanes load one row's 128B contiguously,
// SMEM destination uses the same chunk^(row&7) swizzle as round 7.
// Result writes: direct global stores (round-7 known-good path).
// ============================================================================
template <int COUT>
__global__ void __launch_bounds__(256)
phaseA(const __half* __restrict__ feat, const __half* __restrict__ Wf,
       const int* __restrict__ inlist, const int2* __restrict__ tiles,
       const int* __restrict__ ntiles_p, __half* __restrict__ partial)
{
    constexpr int NO       = COUT / 8;
    constexpr int B_BYTES  = COUT * 128;
    constexpr int A_BYTES  = TILE * 128;
    constexpr int BUF      = A_BYTES + B_BYTES;
    extern __shared__ char smem[];
    const uint32_t smem_base = smem_to_u32(smem);
    const int tid  = threadIdx.x;
    const int wid  = tid >> 5;
    const int lane = tid & 31;
    const int nt   = *ntiles_p;
    const int m0   = wid * 32;

    // stage tile t into buffer buf (A rows + this k's B tile), then commit
    auto stage = [&](int t, int buf) {
        const int2 d = tiles[t];
        const int start = d.x;
        const int k     = d.y & 31;
        const int cnt   = d.y >> 8;
        const char* bs = (const char*)Wf + (size_t)k * B_BYTES;
        const uint32_t base = smem_base + buf * BUF;
        #pragma unroll
        for (int j = tid; j < B_BYTES / 16; j += 256)
            cp_async16(base + A_BYTES + j * 16, bs + (size_t)j * 16);
        // coalesced gather: row r = c*32 + tid/8, chunk = tid%8
        const int ch = tid & 7;
        #pragma unroll
        for (int c = 0; c < 8; c++) {
            const int r = c * 32 + (tid >> 3);
            if (r < cnt) {
                int in_row = inlist[start + r];
                const char* src = (const char*)(feat + (size_t)in_row * 64)
                                  + ch * 16;
                cp_async16(base + r * 128 + ((uint32_t)(ch * 16)
                           ^ ((uint32_t)(r & 7) * 16)), src);
            }
        }
        cp_commit();
    };

    int t = blockIdx.x;
    if (t < nt) stage(t, 0);
    int buf = 0;

    for (; t < nt; t += gridDim.x) {
        const int tn = t + gridDim.x;
        if (tn < nt) { stage(tn, buf ^ 1); cp_wait<1>(); }
        else         { cp_wait<0>(); }
        __syncthreads();

        const int2 d = tiles[t];
        const int start = d.x;
        const int cnt   = d.y >> 8;
        const uint32_t aBase = smem_base + buf * BUF;
        const uint32_t bBase = aBase + A_BYTES;

        float acc[2][NO][4];
        #pragma unroll
        for (int mt = 0; mt < 2; mt++)
            #pragma unroll
            for (int no = 0; no < NO; no++)
                #pragma unroll
                for (int r = 0; r < 4; r++)
                    acc[mt][no][r] = 0.f;

        #pragma unroll
        for (int ko = 0; ko < 4; ko++) {
            uint32_t afrag[2][4];
            const int ch = ko * 2 + (lane >> 4);
            #pragma unroll
            for (int mt = 0; mt < 2; mt++) {
                int r = m0 + mt * 16 + (lane & 15);
                ldmatrix_x4(afrag[mt],
                    aBase + r * 128 + (((uint32_t)ch ^ (uint32_t)(r & 7)) * 16));
            }
            #pragma unroll
            for (int no = 0; no < NO; no++) {
                uint32_t b[2];
                asm volatile("ld.shared.v2.b32 {%0,%1}, [%2];"
                             : "=r"(b[0]), "=r"(b[1])
                             : "r"(bBase + ((ko * NO + no) * 32 + lane) * 8));
                mma16816(acc[0][no], afrag[0], b);
                mma16816(acc[1][no], afrag[1], b);
            }
        }

        // ---- direct global stores (round-7 known-good), tail-guarded ----
        #pragma unroll
        for (int mt = 0; mt < 2; mt++) {
            const int lr = m0 + mt * 16 + (lane >> 2);
            #pragma unroll
            for (int no = 0; no < NO; no++) {
                const int c0 = no * 8 + (lane & 3) * 2;
                if (lr < cnt)
                    *(__half2*)(partial + (size_t)(start + lr) * COUT + c0) =
                        __floats2half2_rn(acc[mt][no][0], acc[mt][no][1]);
                if (lr + 8 < cnt)
                    *(__half2*)(partial + (size_t)(start + lr + 8) * COUT + c0) =
                        __floats2half2_rn(acc[mt][no][2], acc[mt][no][3]);
            }
        }
        __syncthreads();   // all A/B reads done before next stage reuses buf
        buf ^= 1;
    }
}

// ============================================================================
// Phase B (round-7 known-good):
//   out[row,:] = act( sum_j partial[rowpairs[row][j],:] + bias )
// ============================================================================
template <int COUT, bool RELU, typename OUT_T>
__global__ void __launch_bounds__(256)
phaseB(const __half* __restrict__ partial, const int* __restrict__ rowpairs,
       const int* __restrict__ rcnt, const float* __restrict__ bias,
       OUT_T* __restrict__ out)
{
    constexpr int TPR = COUT / 16;
    const int gid = blockIdx.x * 256 + threadIdx.x;
    const int row = gid / TPR;
    const int q   = gid % TPR;

    float acc[16];
    #pragma unroll
    for (int i = 0; i < 16; i++) acc[i] = bias[q * 16 + i];

    const int cnt = rcnt[row];
    const int* rp = rowpairs + (size_t)row * KOFF;
    for (int j = 0; j < cnt; j++) {
        const int p = rp[j];
        const uint4* pr = (const uint4*)(partial + (size_t)p * COUT + q * 16);
        uint4 u0 = pr[0], u1 = pr[1];
        const uint32_t* u = (const uint32_t*)&u0;
        #pragma unroll
        for (int h = 0; h < 4; h++) {
            float2 f = __half22float2(*(const __half2*)&u[h]);
            acc[h * 2]     += f.x;
            acc[h * 2 + 1] += f.y;
        }
        const uint32_t* v = (const uint32_t*)&u1;
        #pragma unroll
        for (int h = 0; h < 4; h++) {
            float2 f = __half22float2(*(const __half2*)&v[h]);
            acc[8 + h * 2]     += f.x;
            acc[8 + h * 2 + 1] += f.y;
        }
    }
    if (RELU) {
        #pragma unroll
        for (int i = 0; i < 16; i++) acc[i] = fmaxf(acc[i], 0.f);
    }
    if constexpr (sizeof(OUT_T) == 2) {
        __half2 hs[8];
        #pragma unroll
        for (int i = 0; i < 8; i++)
            hs[i] = __floats2half2_rn(acc[2 * i], acc[2 * i + 1]);
        uint4* dst = (uint4*)((__half*)out + (size_t)row * COUT + q * 16);
        dst[0] = *(uint4*)&hs[0];
        dst[1] = *(uint4*)&hs[4];
    } else {
        float4* dst = (float4*)((float*)out + (size_t)row * COUT + q * 16);
        #pragma unroll
        for (int i = 0; i < 4; i++)
            dst[i] = make_float4(acc[4 * i], acc[4 * i + 1],
                                 acc[4 * i + 2], acc[4 * i + 3]);
    }
}

// ============================================================================
// Fused prologue: x -> fp16, and W1/W2/W3 -> mma B-fragment order
// ============================================================================
__device__ __forceinline__ void prep_b_elem(const float* __restrict__ W,
                                            __half* __restrict__ Bf,
                                            int Cout, int i) {
    int NOv  = Cout / 8;
    int lane = i & 31;
    int g    = i >> 5;
    int no   = g % NOv;
    int ko   = (g / NOv) % 4;
    int k    = g / (NOv * 4);
    int n    = no * 8 + (lane >> 2);
    int kk0  = ko * 16 + (lane & 3) * 2;
    const float* Wk = W + (size_t)k * 64 * Cout;
    __half h0 = __float2half_rn(Wk[(kk0 + 0) * Cout + n]);
    __half h1 = __float2half_rn(Wk[(kk0 + 1) * Cout + n]);
    __half h2 = __float2half_rn(Wk[(kk0 + 8) * Cout + n]);
    __half h3 = __float2half_rn(Wk[(kk0 + 9) * Cout + n]);
    uint2 v;
    v.x = (uint32_t)__half_as_ushort(h0) | ((uint32_t)__half_as_ushort(h1) << 16);
    v.y = (uint32_t)__half_as_ushort(h2) | ((uint32_t)__half_as_ushort(h3) << 16);
    ((uint2*)Bf)[i] = v;
}

static constexpr int PREP_NP  = NVOX * CIN / 2;
static constexpr int PREP_T12 = KOFF * 4 * 8 * 32;
static constexpr int PREP_T3  = KOFF * 4 * 2 * 32;
static constexpr int PREP_TOT = PREP_NP + 2 * PREP_T12 + PREP_T3;

__global__ void k_prep(const float* __restrict__ x, __half* __restrict__ xh,
                       const float* __restrict__ W1, __half* __restrict__ w1f,
                       const float* __restrict__ W2, __half* __restrict__ w2f,
                       const float* __restrict__ W3, __half* __restrict__ w3f) {
    int i = blockIdx.x * blockDim.x + threadIdx.x;
    if (i < PREP_NP) {
        float2 v = ((const float2*)x)[i];
        ((__half2*)xh)[i] = __floats2half2_rn(v.x, v.y);
    } else if (i < PREP_NP + PREP_T12) {
        prep_b_elem(W1, w1f, 64, i - PREP_NP);
    } else if (i < PREP_NP + 2 * PREP_T12) {
        prep_b_elem(W2, w2f, 64, i - PREP_NP - PREP_T12);
    } else if (i < PREP_TOT) {
        prep_b_elem(W3, w3f, 16, i - PREP_NP - 2 * PREP_T12);
    }
}

// ============================================================================
// kernel_launch
// ============================================================================
extern "C" void kernel_launch(void* const* d_in, const int* in_sizes, int n_in,
                              void* d_out, int out_size) {
    const float* x    = (const float*)d_in[0];
    const int*   nidx = (const int*)  d_in[1];
    const float* W1   = (const float*)d_in[2];
    const float* b1   = (const float*)d_in[3];
    const float* W2   = (const float*)d_in[4];
    const float* b2   = (const float*)d_in[5];
    const float* W3   = (const float*)d_in[6];
    const float* b3   = (const float*)d_in[7];

    __half *xh, *h1, *h2, *w1f, *w2f, *w3f, *part;
    int *inl, *rp, *rc, *kc, *ntl;
    int2* tl;
    cudaGetSymbolAddress((void**)&xh,   g_xh);
    cudaGetSymbolAddress((void**)&h1,   g_h1);
    cudaGetSymbolAddress((void**)&h2,   g_h2);
    cudaGetSymbolAddress((void**)&w1f,  g_W1f);
    cudaGetSymbolAddress((void**)&w2f,  g_W2f);
    cudaGetSymbolAddress((void**)&w3f,  g_W3f);
    cudaGetSymbolAddress((void**)&part, g_partial);
    cudaGetSymbolAddress((void**)&inl,  g_inlist);
    cudaGetSymbolAddress((void**)&rp,   g_rowpairs);
    cudaGetSymbolAddress((void**)&rc,   g_rcnt);
    cudaGetSymbolAddress((void**)&kc,   g_kcnt);
    cudaGetSymbolAddress((void**)&tl,   g_tiles);
    cudaGetSymbolAddress((void**)&ntl,  g_ntiles);

    // ---- fork: pair-list branch (reads only nidx) runs parallel to k_prep ----
    cudaStream_t s1;
    cudaStreamCreateWithFlags(&s1, cudaStreamNonBlocking);
    cudaEvent_t e0, e1;
    cudaEventCreateWithFlags(&e0, cudaEventDisableTiming);
    cudaEventCreateWithFlags(&e1, cudaEventDisableTiming);

    cudaEventRecord(e0, 0);
    cudaStreamWaitEvent(s1, e0, 0);

    k_prep<<<(PREP_TOT + 255) / 256, 256>>>(x, xh, W1, w1f, W2, w2f, W3, w3f);

    cudaMemsetAsync(kc, 0, KOFF * sizeof(int), s1);
    k_fill<<<NROWB, NBLK, 0, s1>>>(nidx, kc, inl, rp, rc);
    k_tiles<<<1, 32, 0, s1>>>(kc, tl, ntl);

    cudaEventRecord(e1, s1);
    cudaStreamWaitEvent(0, e1, 0);

    constexpr int SZA64 = 2 * (TILE * 128 + 64 * 128);  // 81920
    constexpr int SZA16 = 2 * (TILE * 128 + 16 * 128);  // 69632
    constexpr int GA = 296;                             // 2 CTAs/SM persistent
    cudaFuncSetAttribute((const void*)phaseA<64>,
                         cudaFuncAttributeMaxDynamicSharedMemorySize, SZA64);
    cudaFuncSetAttribute((const void*)phaseA<16>,
                         cudaFuncAttributeMaxDynamicSharedMemorySize, SZA16);

    // layer 1
    phaseA<64><<<GA, 256, SZA64>>>(xh, w1f, inl, tl, ntl, part);
    phaseB<64, true, __half><<<NVOX * 4 / 256, 256>>>(part, rp, rc, b1, h1);
    // layer 2
    phaseA<64><<<GA, 256, SZA64>>>(h1, w2f, inl, tl, ntl, part);
    phaseB<64, true, __half><<<NVOX * 4 / 256, 256>>>(part, rp, rc, b2, h2);
    // layer 3
    phaseA<16><<<GA, 256, SZA16>>>(h2, w3f, inl, tl, ntl, part);
    phaseB<16, false, float><<<NVOX / 256, 256>>>(part, rp, rc, b3,
                                                  (float*)d_out);

    cudaEventDestroy(e0);
    cudaEventDestroy(e1);
    cudaStreamDestroy(s1);
}

// round 11
// speedup vs baseline: 1.7343x; 1.0241x over previous
#include <cuda_runtime.h>
#include <cuda_fp16.h>
#include <cstdint>

// ============================================================================
// Problem sizes
// ============================================================================
static constexpr int NVOX  = 65536;
static constexpr int CIN   = 64;
static constexpr int CH    = 64;
static constexpr int COUT3 = 16;
static constexpr int KOFF  = 27;
static constexpr int NBLK  = 256;             // rows per fill block
static constexpr int NROWB = NVOX / NBLK;     // 256 blocks
static constexpr int PMAX  = KOFF * NVOX;     // fixed per-k segments of NVOX
static constexpr int TILE  = 128;             // pair rows per phase-A tile
static constexpr int TMAXT = KOFF * (NVOX / TILE);
static constexpr int NWARP = NBLK / 32;       // 8

// ============================================================================
// Device scratch (no dynamic allocation allowed)
// ============================================================================
__device__ __half g_xh[NVOX * CIN];
__device__ __half g_h1[NVOX * CH];
__device__ __half g_h2[NVOX * CH];
__device__ __half g_W1f[KOFF * CH * CIN];
__device__ __half g_W2f[KOFF * CH * CH];
__device__ __half g_W3f[KOFF * COUT3 * CH];

__device__ int    g_inlist[PMAX];                   // input row per pair
__device__ __half g_partial[(size_t)PMAX * 64];     // pair partial rows
__device__ int    g_rowpairs[NVOX * KOFF];          // per-row pair ids
__device__ int    g_rcnt[NVOX];
__device__ int    g_kcnt[KOFF];                     // pairs per offset
__device__ int2   g_tiles[TMAXT];                   // {start, k | cnt<<8}
__device__ int    g_ntiles[1];

// ============================================================================
// PTX helpers
// ============================================================================
__device__ __forceinline__ uint32_t smem_to_u32(const void* smem_ptr) {
    uint32_t addr;
    asm("{ .reg .u64 tmp; cvta.to.shared.u64 tmp, %1; cvt.u32.u64 %0, tmp; }"
        : "=r"(addr) : "l"(smem_ptr));
    return addr;
}
__device__ __forceinline__ void cp_async16(uint32_t dst, const void* src) {
    asm volatile("cp.async.cg.shared.global [%0], [%1], 16;"
                 :: "r"(dst), "l"(src));
}
__device__ __forceinline__ void cp_commit() {
    asm volatile("cp.async.commit_group;");
}
template <int N>
__device__ __forceinline__ void cp_wait() {
    asm volatile("cp.async.wait_group %0;" :: "n"(N));
}
__device__ __forceinline__ void ldmatrix_x4(uint32_t* a, uint32_t addr) {
    asm volatile("ldmatrix.sync.aligned.m8n8.x4.shared.b16 {%0,%1,%2,%3}, [%4];"
                 : "=r"(a[0]), "=r"(a[1]), "=r"(a[2]), "=r"(a[3]) : "r"(addr));
}
__device__ __forceinline__ void mma16816(float* c, const uint32_t* a,
                                         const uint32_t* b) {
    asm volatile(
        "mma.sync.aligned.m16n8k16.row.col.f32.f16.f16.f32 "
        "{%0,%1,%2,%3}, {%4,%5,%6,%7}, {%8,%9}, {%0,%1,%2,%3};"
        : "+f"(c[0]), "+f"(c[1]), "+f"(c[2]), "+f"(c[3])
        : "r"(a[0]), "r"(a[1]), "r"(a[2]), "r"(a[3]), "r"(b[0]), "r"(b[1]));
}

// ============================================================================
// Pair-list construction: ONE pass over nidx. Pairs for offset k land in the
// fixed segment [k*NVOX, ...) via block-aggregated atomicAdd. Placement order
// is nondeterministic but output-invariant (partial[p] depends only on
// (inlist[p], k); phaseB sums in fixed slot order).
// ============================================================================
__global__ void __launch_bounds__(NBLK)
k_fill(const int* __restrict__ nidx, int* __restrict__ kcnt,
       int* __restrict__ inlist, int* __restrict__ rowpairs,
       int* __restrict__ rcnt) {
    __shared__ int wpre[KOFF][NWARP];
    __shared__ int kbase[KOFF];
    const int t = threadIdx.x, b = blockIdx.x;
    const int w = t >> 5, lane = t & 31;
    const int row = b * NBLK + t;
    const int* ip = nidx + (size_t)row * KOFF;
    unsigned m = 0;
    #pragma unroll
    for (int k = 0; k < KOFF; k++)
        m |= (unsigned)(ip[k] >= 0) << k;
    #pragma unroll
    for (int k = 0; k < KOFF; k++) {
        unsigned bal = __ballot_sync(0xFFFFFFFFu, (m >> k) & 1u);
        if (lane == 0) wpre[k][w] = __popc(bal);
    }
    __syncthreads();
    if (t < KOFF) {
        int run = 0;
        #pragma unroll
        for (int g = 0; g < NWARP; g++) {
            int c = wpre[t][g];
            wpre[t][g] = run;
            run += c;
        }
        kbase[t] = atomicAdd(&kcnt[t], run);
    }
    __syncthreads();
    int slot = 0;
    const unsigned lt = (lane == 0) ? 0u : (0xFFFFFFFFu >> (32 - lane));
    #pragma unroll
    for (int k = 0; k < KOFF; k++) {
        const unsigned v = (m >> k) & 1u;
        const unsigned bal = __ballot_sync(0xFFFFFFFFu, v);
        if (v) {
            int p = k * NVOX + kbase[k] + wpre[k][w] + __popc(bal & lt);
            inlist[p] = ip[k];
            rowpairs[(size_t)row * KOFF + slot] = p;
            slot++;
        }
    }
    rcnt[row] = slot;
}

__global__ void k_tiles(const int* __restrict__ kcnt, int2* __restrict__ tiles,
                        int* __restrict__ ntiles) {
    __shared__ int tc[KOFF], tb[KOFF];
    const int t = threadIdx.x;
    if (t < KOFF) tc[t] = (kcnt[t] + TILE - 1) / TILE;
    __syncthreads();
    if (t == 0) {
        int run = 0;
        for (int k = 0; k < KOFF; k++) { tb[k] = run; run += tc[k]; }
        *ntiles = run;
    }
    __syncthreads();
    if (t < KOFF) {
        const int cnt = kcnt[t];
        for (int j = 0; j < tc[t]; j++)
            tiles[tb[t] + j] = make_int2(t * NVOX + j * TILE,
                                         t | (min(TILE, cnt - j * TILE) << 8));
    }
}

// ============================================================================
// Phase A (double-buffered, 128 threads, TILE=128, 4 CTAs/SM):
//   per tile (one k): partial[p,:] = feat[inlist[p],:] @ W[k]
// Gather is coalesced: 8 consecutive lanes load one row's 128B contiguously,
// SMEM destination uses the chunk^(row&7) swizzle.
// Result writes: direct global stores (known-good path).
// ============================================================================
template <int COUT>
__global__ void __launch_bounds__(128, 4)
phaseA(const __half* __restrict__ feat, const __half* __restrict__ Wf,
       const int* __restrict__ inlist, const int2* __restrict__ tiles,
       const int* __restrict__ ntiles_p, __half* __restrict__ partial)
{
    constexpr int NO       = COUT / 8;
    constexpr int B_BYTES  = COUT * 128;
    constexpr int A_BYTES  = TILE * 128;     // 16384
    constexpr int BUF      = A_BYTES + B_BYTES;
    extern __shared__ char smem[];
    const uint32_t smem_base = smem_to_u32(smem);
    const int tid  = threadIdx.x;
    const int wid  = tid >> 5;               // 0..3
    const int lane = tid & 31;
    const int nt   = *ntiles_p;
    const int m0   = wid * 32;               // 4 warps x m32 = 128 rows

    // stage tile t into buffer buf (A rows + this k's B tile), then commit
    auto stage = [&](int t, int buf) {
        const int2 d = tiles[t];
        const int start = d.x;
        const int k     = d.y & 31;
        const int cnt   = d.y >> 8;
        const char* bs = (const char*)Wf + (size_t)k * B_BYTES;
        const uint32_t base = smem_base + buf * BUF;
        #pragma unroll
        for (int j = tid; j < B_BYTES / 16; j += 128)
            cp_async16(base + A_BYTES + j * 16, bs + (size_t)j * 16);
        // coalesced gather: row r = c*16 + tid/8, chunk = tid%8
        const int ch = tid & 7;
        #pragma unroll
        for (int c = 0; c < 8; c++) {
            const int r = c * 16 + (tid >> 3);
            if (r < cnt) {
                int in_row = inlist[start + r];
                const char* src = (const char*)(feat + (size_t)in_row * 64)
                                  + ch * 16;
                cp_async16(base + r * 128 + ((uint32_t)(ch * 16)
                           ^ ((uint32_t)(r & 7) * 16)), src);
            }
        }
        cp_commit();
    };

    int t = blockIdx.x;
    if (t < nt) stage(t, 0);
    int buf = 0;

    for (; t < nt; t += gridDim.x) {
        const int tn = t + gridDim.x;
        if (tn < nt) { stage(tn, buf ^ 1); cp_wait<1>(); }
        else         { cp_wait<0>(); }
        __syncthreads();

        const int2 d = tiles[t];
        const int start = d.x;
        const int cnt   = d.y >> 8;
        const uint32_t aBase = smem_base + buf * BUF;
        const uint32_t bBase = aBase + A_BYTES;

        float acc[2][NO][4];
        #pragma unroll
        for (int mt = 0; mt < 2; mt++)
            #pragma unroll
            for (int no = 0; no < NO; no++)
                #pragma unroll
                for (int r = 0; r < 4; r++)
                    acc[mt][no][r] = 0.f;

        #pragma unroll
        for (int ko = 0; ko < 4; ko++) {
            uint32_t afrag[2][4];
            const int ch = ko * 2 + (lane >> 4);
            #pragma unroll
            for (int mt = 0; mt < 2; mt++) {
                int r = m0 + mt * 16 + (lane & 15);
                ldmatrix_x4(afrag[mt],
                    aBase + r * 128 + (((uint32_t)ch ^ (uint32_t)(r & 7)) * 16));
            }
            #pragma unroll
            for (int no = 0; no < NO; no++) {
                uint32_t b[2];
                asm volatile("ld.shared.v2.b32 {%0,%1}, [%2];"
                             : "=r"(b[0]), "=r"(b[1])
                             : "r"(bBase + ((ko * NO + no) * 32 + lane) * 8));
                mma16816(acc[0][no], afrag[0], b);
                mma16816(acc[1][no], afrag[1], b);
            }
        }

        // ---- direct global stores, tail-guarded ----
        #pragma unroll
        for (int mt = 0; mt < 2; mt++) {
            const int lr = m0 + mt * 16 + (lane >> 2);
            #pragma unroll
            for (int no = 0; no < NO; no++) {
                const int c0 = no * 8 + (lane & 3) * 2;
                if (lr < cnt)
                    *(__half2*)(partial + (size_t)(start + lr) * COUT + c0) =
                        __floats2half2_rn(acc[mt][no][0], acc[mt][no][1]);
                if (lr + 8 < cnt)
                    *(__half2*)(partial + (size_t)(start + lr + 8) * COUT + c0) =
                        __floats2half2_rn(acc[mt][no][2], acc[mt][no][3]);
            }
        }
        __syncthreads();   // all A/B reads done before next stage reuses buf
        buf ^= 1;
    }
}

// ============================================================================
// Phase B: out[row,:] = act( sum_j partial[rowpairs[row][j],:] + bias )
// ============================================================================
template <int COUT, bool RELU, typename OUT_T>
__global__ void __launch_bounds__(256)
phaseB(const __half* __restrict__ partial, const int* __restrict__ rowpairs,
       const int* __restrict__ rcnt, const float* __restrict__ bias,
       OUT_T* __restrict__ out)
{
    constexpr int TPR = COUT / 16;
    const int gid = blockIdx.x * 256 + threadIdx.x;
    const int row = gid / TPR;
    const int q   = gid % TPR;

    float acc[16];
    #pragma unroll
    for (int i = 0; i < 16; i++) acc[i] = bias[q * 16 + i];

    const int cnt = rcnt[row];
    const int* rp = rowpairs + (size_t)row * KOFF;
    for (int j = 0; j < cnt; j++) {
        const int p = rp[j];
        const uint4* pr = (const uint4*)(partial + (size_t)p * COUT + q * 16);
        uint4 u0 = pr[0], u1 = pr[1];
        const uint32_t* u = (const uint32_t*)&u0;
        #pragma unroll
        for (int h = 0; h < 4; h++) {
            float2 f = __half22float2(*(const __half2*)&u[h]);
            acc[h * 2]     += f.x;
            acc[h * 2 + 1] += f.y;
        }
        const uint32_t* v = (const uint32_t*)&u1;
        #pragma unroll
        for (int h = 0; h < 4; h++) {
            float2 f = __half22float2(*(const __half2*)&v[h]);
            acc[8 + h * 2]     += f.x;
            acc[8 + h * 2 + 1] += f.y;
        }
    }
    if (RELU) {
        #pragma unroll
        for (int i = 0; i < 16; i++) acc[i] = fmaxf(acc[i], 0.f);
    }
    if constexpr (sizeof(OUT_T) == 2) {
        __half2 hs[8];
        #pragma unroll
        for (int i = 0; i < 8; i++)
            hs[i] = __floats2half2_rn(acc[2 * i], acc[2 * i + 1]);
        uint4* dst = (uint4*)((__half*)out + (size_t)row * COUT + q * 16);
        dst[0] = *(uint4*)&hs[0];
        dst[1] = *(uint4*)&hs[4];
    } else {
        float4* dst = (float4*)((float*)out + (size_t)row * COUT + q * 16);
        #pragma unroll
        for (int i = 0; i < 4; i++)
            dst[i] = make_float4(acc[4 * i], acc[4 * i + 1],
                                 acc[4 * i + 2], acc[4 * i + 3]);
    }
}

// ============================================================================
// Fused prologue: x -> fp16, and W1/W2/W3 -> mma B-fragment order
// ============================================================================
__device__ __forceinline__ void prep_b_elem(const float* __restrict__ W,
                                            __half* __restrict__ Bf,
                                            int Cout, int i) {
    int NOv  = Cout / 8;
    int lane = i & 31;
    int g    = i >> 5;
    int no   = g % NOv;
    int ko   = (g / NOv) % 4;
    int k    = g / (NOv * 4);
    int n    = no * 8 + (lane >> 2);
    int kk0  = ko * 16 + (lane & 3) * 2;
    const float* Wk = W + (size_t)k * 64 * Cout;
    __half h0 = __float2half_rn(Wk[(kk0 + 0) * Cout + n]);
    __half h1 = __float2half_rn(Wk[(kk0 + 1) * Cout + n]);
    __half h2 = __float2half_rn(Wk[(kk0 + 8) * Cout + n]);
    __half h3 = __float2half_rn(Wk[(kk0 + 9) * Cout + n]);
    uint2 v;
    v.x = (uint32_t)__half_as_ushort(h0) | ((uint32_t)__half_as_ushort(h1) << 16);
    v.y = (uint32_t)__half_as_ushort(h2) | ((uint32_t)__half_as_ushort(h3) << 16);
    ((uint2*)Bf)[i] = v;
}

static constexpr int PREP_NP  = NVOX * CIN / 2;
static constexpr int PREP_T12 = KOFF * 4 * 8 * 32;
static constexpr int PREP_T3  = KOFF * 4 * 2 * 32;
static constexpr int PREP_TOT = PREP_NP + 2 * PREP_T12 + PREP_T3;

__global__ void k_prep(const float* __restrict__ x, __half* __restrict__ xh,
                       const float* __restrict__ W1, __half* __restrict__ w1f,
                       const float* __restrict__ W2, __half* __restrict__ w2f,
                       const float* __restrict__ W3, __half* __restrict__ w3f) {
    int i = blockIdx.x * blockDim.x + threadIdx.x;
    if (i < PREP_NP) {
        float2 v = ((const float2*)x)[i];
        ((__half2*)xh)[i] = __floats2half2_rn(v.x, v.y);
    } else if (i < PREP_NP + PREP_T12) {
        prep_b_elem(W1, w1f, 64, i - PREP_NP);
    } else if (i < PREP_NP + 2 * PREP_T12) {
        prep_b_elem(W2, w2f, 64, i - PREP_NP - PREP_T12);
    } else if (i < PREP_TOT) {
        prep_b_elem(W3, w3f, 16, i - PREP_NP - 2 * PREP_T12);
    }
}

// ============================================================================
// kernel_launch
// ============================================================================
extern "C" void kernel_launch(void* const* d_in, const int* in_sizes, int n_in,
                              void* d_out, int out_size) {
    const float* x    = (const float*)d_in[0];
    const int*   nidx = (const int*)  d_in[1];
    const float* W1   = (const float*)d_in[2];
    const float* b1   = (const float*)d_in[3];
    const float* W2   = (const float*)d_in[4];
    const float* b2   = (const float*)d_in[5];
    const float* W3   = (const float*)d_in[6];
    const float* b3   = (const float*)d_in[7];

    __half *xh, *h1, *h2, *w1f, *w2f, *w3f, *part;
    int *inl, *rp, *rc, *kc, *ntl;
    int2* tl;
    cudaGetSymbolAddress((void**)&xh,   g_xh);
    cudaGetSymbolAddress((void**)&h1,   g_h1);
    cudaGetSymbolAddress((void**)&h2,   g_h2);
    cudaGetSymbolAddress((void**)&w1f,  g_W1f);
    cudaGetSymbolAddress((void**)&w2f,  g_W2f);
    cudaGetSymbolAddress((void**)&w3f,  g_W3f);
    cudaGetSymbolAddress((void**)&part, g_partial);
    cudaGetSymbolAddress((void**)&inl,  g_inlist);
    cudaGetSymbolAddress((void**)&rp,   g_rowpairs);
    cudaGetSymbolAddress((void**)&rc,   g_rcnt);
    cudaGetSymbolAddress((void**)&kc,   g_kcnt);
    cudaGetSymbolAddress((void**)&tl,   g_tiles);
    cudaGetSymbolAddress((void**)&ntl,  g_ntiles);

    // ---- fork: pair-list branch (reads only nidx) runs parallel to k_prep ----
    cudaStream_t s1;
    cudaStreamCreateWithFlags(&s1, cudaStreamNonBlocking);
    cudaEvent_t e0, e1;
    cudaEventCreateWithFlags(&e0, cudaEventDisableTiming);
    cudaEventCreateWithFlags(&e1, cudaEventDisableTiming);

    cudaEventRecord(e0, 0);
    cudaStreamWaitEvent(s1, e0, 0);

    k_prep<<<(PREP_TOT + 255) / 256, 256>>>(x, xh, W1, w1f, W2, w2f, W3, w3f);

    cudaMemsetAsync(kc, 0, KOFF * sizeof(int), s1);
    k_fill<<<NROWB, NBLK, 0, s1>>>(nidx, kc, inl, rp, rc);
    k_tiles<<<1, 32, 0, s1>>>(kc, tl, ntl);

    cudaEventRecord(e1, s1);
    cudaStreamWaitEvent(0, e1, 0);

    constexpr int SZA64 = 2 * (TILE * 128 + 64 * 128);  // 49152
    constexpr int SZA16 = 2 * (TILE * 128 + 16 * 128);  // 36864
    constexpr int GA = 592;                             // 4 CTAs/SM persistent
    cudaFuncSetAttribute((const void*)phaseA<64>,
                         cudaFuncAttributeMaxDynamicSharedMemorySize, SZA64);
    cudaFuncSetAttribute((const void*)phaseA<16>,
                         cudaFuncAttributeMaxDynamicSharedMemorySize, SZA16);

    // layer 1
    phaseA<64><<<GA, 128, SZA64>>>(xh, w1f, inl, tl, ntl, part);
    phaseB<64, true, __half><<<NVOX * 4 / 256, 256>>>(part, rp, rc, b1, h1);
    // layer 2
    phaseA<64><<<GA, 128, SZA64>>>(h1, w2f, inl, tl, ntl, part);
    phaseB<64, true, __half><<<NVOX * 4 / 256, 256>>>(part, rp, rc, b2, h2);
    // layer 3
    phaseA<16><<<GA, 128, SZA16>>>(h2, w3f, inl, tl, ntl, part);
    phaseB<16, false, float><<<NVOX / 256, 256>>>(part, rp, rc, b3,
                                                  (float*)d_out);

    cudaEventDestroy(e0);
    cudaEventDestroy(e1);
    cudaStreamDestroy(s1);
}